// round 10
// baseline (speedup 1.0000x reference)
#include <cuda_runtime.h>

#define Bn 64
#define Tn 128
#define Sn 128
#define Cn 512
#define Hn 8
#define DHn 64
#define FFn 2048
#define Ln 6

// ---------------- scratch (device globals; no allocation allowed) ----------------
__device__ float g_q[Bn*Tn*Cn];          // [B*T, H*DH]
__device__ float g_k[Bn*Sn*Cn];
__device__ float g_v[Bn*Sn*Cn];
__device__ float g_y[Bn*Tn*Cn];          // pre-norm y = x + residual
__device__ float g_h[(size_t)Bn*Tn*FFn]; // FF hidden (tf32-rounded)
__device__ float g_xt[Bn*Tn*Cn];         // tf32 mirror of normalized x
__device__ float g_enct[Bn*Sn*Cn];       // tf32 mirror of encoder output
__device__ float g_ps[Bn*8], g_ps2[Bn*8];// LN partial stats (slots)
__device__ float g_mu[Bn], g_inv[Bn];    // committed LN stats of previous stage
__device__ float g_wsaq[Ln*Cn*Cn], g_wsak[Ln*Cn*Cn], g_wsav[Ln*Cn*Cn];
__device__ float g_wcaq[Ln*Cn*Cn], g_wcak[Ln*Cn*Cn], g_wcav[Ln*Cn*Cn];
__device__ float g_wff1[(size_t)Ln*Cn*FFn];
__device__ float g_wff2[(size_t)Ln*FFn*Cn];

// ---------------- tf32 helpers ----------------
__device__ __forceinline__ unsigned f2tf(float f) {
    unsigned u;
    asm("cvt.rna.tf32.f32 %0, %1;" : "=r"(u) : "f"(f));
    return u;
}
__device__ __forceinline__ float f2tff(float f) { return __uint_as_float(f2tf(f)); }
__device__ __forceinline__ void mma8(float c[4], const unsigned a[4], const unsigned b[2]) {
    asm volatile("mma.sync.aligned.m16n8k8.row.col.f32.tf32.tf32.f32 "
        "{%0,%1,%2,%3}, {%4,%5,%6,%7}, {%8,%9}, {%0,%1,%2,%3};"
        : "+f"(c[0]), "+f"(c[1]), "+f"(c[2]), "+f"(c[3])
        : "r"(a[0]), "r"(a[1]), "r"(a[2]), "r"(a[3]), "r"(b[0]), "r"(b[1]));
}
__device__ __forceinline__ void cpasync16(void* s, const void* g) {
    unsigned sa = (unsigned)__cvta_generic_to_shared(s);
    asm volatile("cp.async.cg.shared.global [%0], [%1], 16;" :: "r"(sa), "l"(g));
}

// ---------------- conversion kernels (once per launch) ----------------
__global__ void cvt_kernel(const float* __restrict__ src, float* __restrict__ dst, int n) {
    int i = blockIdx.x * 256 + threadIdx.x;
    if (i < n) dst[i] = f2tff(src[i]);
}
// src [L,H,C,DH] -> dst [L,C,H*DH] with tf32 rounding
__global__ void cvt_qkvw_kernel(const float* __restrict__ src, float* __restrict__ dst) {
    int i = blockIdx.x * 256 + threadIdx.x;
    int d = i & 63, c = (i >> 6) & 511, h = (i >> 15) & 7, l = i >> 18;
    dst[((size_t)(l * Cn + c)) * 512 + h * 64 + d] = f2tff(src[i]);
}
__global__ void init_stats_kernel() {
    int i = threadIdx.x;
    if (i < Bn) { g_mu[i] = 0.f; g_inv[i] = 1.f; }
}

// -------- unified tf32 GEMM: block 128x256, warp 64x64, 3-stage cp.async --------------
// Physical-k permutation: logical k-lane (t, t+4) <-> physical columns (2t, 2t+1),
// applied identically to A and B fragments (bijective per k8 group -> same result).
#define ASTR 40          // 8 mod 32 -> conflict-free LDS.64 A fragments
#define BSTR 260         // 4 mod 16 -> conflict-free LDS.32 B fragments
#define ABUF (128*ASTR)
#define BBUF (32*BSTR)
#define NSTG 3
#define GEMM_SMEM ((NSTG*(ABUF+BBUF)) * (int)sizeof(float))   // 161280 B

// EPI: 0 = bias only, 1 = relu + tf32 round, 2 = residual-from-y add + LN partial stats
template<int EPI>
__device__ __forceinline__ void gemm_core(
    const float* __restrict__ A, const float* __restrict__ W,
    const float* __restrict__ bias, float* __restrict__ outp,
    const float* __restrict__ resid,
    int N, int K, int rowTile, int colTile, float* smem)
{
    float* As = smem;
    float* Bs = smem + NSTG * ABUF;

    int tid = threadIdx.x, wid = tid >> 5, lane = tid & 31;
    int wm = wid >> 2, wn = wid & 3;        // 2(M) x 4(N) warps
    int g = lane >> 2, t = lane & 3;

    float acc[4][8][4];
    #pragma unroll
    for (int i = 0; i < 4; i++)
        #pragma unroll
        for (int j = 0; j < 8; j++)
            #pragma unroll
            for (int q = 0; q < 4; q++) acc[i][j][q] = 0.f;

    const float* Ab = A + (size_t)rowTile * K;
    const float* Wb = W + colTile;
    int KT = K >> 5;

    // prologue: stage slabs 0, 1
    #pragma unroll
    for (int st = 0; st < 2; st++) {
        int k0 = st << 5;
        float* Ad = As + st * ABUF;
        float* Bd = Bs + st * BBUF;
        #pragma unroll
        for (int j = 0; j < 4; j++) {       // A: 128x32 = 1024 float4
            int q = tid + j * 256; int r = q >> 3, ko = (q & 7) * 4;
            cpasync16(&Ad[r * ASTR + ko], &Ab[(size_t)r * K + k0 + ko]);
        }
        #pragma unroll
        for (int j = 0; j < 8; j++) {       // B: 32x256 = 2048 float4
            int q = tid + j * 256; int kk = q >> 6, no = (q & 63) * 4;
            cpasync16(&Bd[kk * BSTR + no], &Wb[(size_t)(k0 + kk) * N + no]);
        }
        asm volatile("cp.async.commit_group;");
    }

    int buf = 0;
    for (int kt = 0; kt < KT; kt++) {
        asm volatile("cp.async.wait_group 1;");
        __syncthreads();

        const float* Af = As + buf * ABUF;
        const float* Bf = Bs + buf * BBUF;
        const unsigned* Bu = (const unsigned*)Bf;
        #pragma unroll
        for (int ks = 0; ks < 4; ks++) {
            int c0 = ks * 8 + 2 * t;            // physical column pair (c0, c0+1)
            unsigned a[4][4], bf[8][2];
            #pragma unroll
            for (int i = 0; i < 4; i++) {
                int r = wm * 64 + i * 16 + g;
                float2 p0 = *(const float2*)&Af[r * ASTR + c0];
                float2 p1 = *(const float2*)&Af[(r + 8) * ASTR + c0];
                a[i][0] = __float_as_uint(p0.x);
                a[i][2] = __float_as_uint(p0.y);
                a[i][1] = __float_as_uint(p1.x);
                a[i][3] = __float_as_uint(p1.y);
            }
            #pragma unroll
            for (int j = 0; j < 8; j++) {
                int n = wn * 64 + j * 8 + g;
                bf[j][0] = Bu[c0 * BSTR + n];
                bf[j][1] = Bu[(c0 + 1) * BSTR + n];
            }
            #pragma unroll
            for (int i = 0; i < 4; i++)
                #pragma unroll
                for (int j = 0; j < 8; j++)
                    mma8(acc[i][j], a[i], bf[j]);
        }

        // prefetch slab kt+2 into the free buffer
        if (kt + 2 < KT) {
            int k0 = (kt + 2) << 5;
            int nb = kt + 2; nb -= (nb / NSTG) * NSTG;
            float* Ad = As + nb * ABUF;
            float* Bd = Bs + nb * BBUF;
            #pragma unroll
            for (int j = 0; j < 4; j++) {
                int q = tid + j * 256; int r = q >> 3, ko = (q & 7) * 4;
                cpasync16(&Ad[r * ASTR + ko], &Ab[(size_t)r * K + k0 + ko]);
            }
            #pragma unroll
            for (int j = 0; j < 8; j++) {
                int q = tid + j * 256; int kk = q >> 6, no = (q & 63) * 4;
                cpasync16(&Bd[kk * BSTR + no], &Wb[(size_t)(k0 + kk) * N + no]);
            }
        }
        asm volatile("cp.async.commit_group;");

        buf++; if (buf == NSTG) buf = 0;
    }

    float s = 0.f, s2 = 0.f;
    float mu = 0.f, inv = 1.f;
    if (EPI == 2) { mu = g_mu[rowTile >> 7]; inv = g_inv[rowTile >> 7]; }
    #pragma unroll
    for (int i = 0; i < 4; i++) {
        int r0 = rowTile + wm * 64 + i * 16 + g;
        #pragma unroll
        for (int j = 0; j < 8; j++) {
            int c = colTile + wn * 64 + j * 8 + 2 * t;
            float b0 = bias[c], b1 = bias[c + 1];
            float v0 = acc[i][j][0] + b0, v1 = acc[i][j][1] + b1;
            float v2 = acc[i][j][2] + b0, v3 = acc[i][j][3] + b1;
            if (EPI == 1) {
                v0 = f2tff(fmaxf(v0, 0.f)); v1 = f2tff(fmaxf(v1, 0.f));
                v2 = f2tff(fmaxf(v2, 0.f)); v3 = f2tff(fmaxf(v3, 0.f));
            }
            if (EPI == 2) {
                float2 x0 = *(const float2*)&resid[(size_t)r0 * N + c];
                float2 x1 = *(const float2*)&resid[(size_t)(r0 + 8) * N + c];
                v0 += (x0.x - mu) * inv; v1 += (x0.y - mu) * inv;
                v2 += (x1.x - mu) * inv; v3 += (x1.y - mu) * inv;
                s  += v0 + v1 + v2 + v3;
                s2 += v0*v0 + v1*v1 + v2*v2 + v3*v3;
            }
            *(float2*)&outp[(size_t)r0 * N + c]       = make_float2(v0, v1);
            *(float2*)&outp[(size_t)(r0 + 8) * N + c] = make_float2(v2, v3);
        }
    }

    if (EPI == 2) {
        __shared__ float rs[8], rs2[8];
        #pragma unroll
        for (int o = 16; o > 0; o >>= 1) {
            s  += __shfl_xor_sync(0xffffffffu, s, o);
            s2 += __shfl_xor_sync(0xffffffffu, s2, o);
        }
        if (lane == 0) { rs[wid] = s; rs2[wid] = s2; }
        __syncthreads();
        if (tid == 0) {
            float ts = 0.f, ts2 = 0.f;
            #pragma unroll
            for (int i = 0; i < 8; i++) { ts += rs[i]; ts2 += rs2[i]; }
            int slot = (rowTile >> 7) * 8 + (colTile >> 8);
            g_ps[slot] = ts; g_ps2[slot] = ts2;
        }
    }
}

__global__ __launch_bounds__(256, 1) void gemm_qkv_kernel(
    const float* __restrict__ Aq, const float* __restrict__ Akv,
    const float* __restrict__ wq, const float* __restrict__ wk, const float* __restrict__ wv,
    const float* __restrict__ bq, const float* __restrict__ bk, const float* __restrict__ bv)
{
    extern __shared__ float smem[];
    const float* A; const float* W; const float* bias; float* outp;
    int z = blockIdx.z;
    if (z == 0)      { A = Aq;  W = wq; bias = bq; outp = g_q; }
    else if (z == 1) { A = Akv; W = wk; bias = bk; outp = g_k; }
    else             { A = Akv; W = wv; bias = bv; outp = g_v; }
    gemm_core<0>(A, W, bias, outp, nullptr, 512, 512,
                 blockIdx.y * 128, blockIdx.x * 256, smem);
}

__global__ __launch_bounds__(256, 1) void gemm_ff1_kernel(
    const float* __restrict__ A, const float* __restrict__ W,
    const float* __restrict__ bias)
{
    extern __shared__ float smem[];
    gemm_core<1>(A, W, bias, g_h, nullptr, FFn, Cn,
                 blockIdx.y * 128, blockIdx.x * 256, smem);
}
__global__ __launch_bounds__(256, 1) void gemm_ff2_kernel(
    const float* __restrict__ W, const float* __restrict__ bias)
{
    extern __shared__ float smem[];
    gemm_core<2>(g_h, W, bias, g_y, g_y, Cn, FFn,
                 blockIdx.y * 128, blockIdx.x * 256, smem);
}

// ---------------- fused attention per (b,h) + residual-from-y add + LN stats ----------
#define QS 68
#define PS 132
#define ATTN_SMEM ((3*128*QS + 128*PS) * (int)sizeof(float))   // 172032 B

__global__ __launch_bounds__(256) void attn_kernel()
{
    extern __shared__ float sm[];
    float* Qs = sm;
    float* Ks = sm + 128*QS;
    float* Vs = sm + 2*128*QS;
    float* Ps = sm + 3*128*QS;

    int bh = blockIdx.x;
    int h = bh & (Hn - 1);
    int b = bh >> 3;
    int tid = threadIdx.x, wid = tid >> 5, lane = tid & 31;
    int g = lane >> 2, t = lane & 3;

    const float* qg = g_q + (size_t)b * Tn * Cn + h * DHn;
    const float* kg = g_k + (size_t)b * Sn * Cn + h * DHn;
    const float* vg = g_v + (size_t)b * Sn * Cn + h * DHn;

    for (int e = tid; e < Tn * DHn / 4; e += 256) {
        int r = e >> 4, d = (e & 15) * 4;
        size_t gi = (size_t)r * Cn + d;
        float4 q = *(const float4*)&qg[gi];
        float4 k = *(const float4*)&kg[gi];
        float4 v = *(const float4*)&vg[gi];
        float* qd = &Qs[r*QS + d];
        qd[0] = f2tff(q.x * 0.125f); qd[1] = f2tff(q.y * 0.125f);
        qd[2] = f2tff(q.z * 0.125f); qd[3] = f2tff(q.w * 0.125f);
        float* kd = &Ks[r*QS + d];
        kd[0] = f2tff(k.x); kd[1] = f2tff(k.y); kd[2] = f2tff(k.z); kd[3] = f2tff(k.w);
        float* vd = &Vs[r*QS + d];
        vd[0] = f2tff(v.x); vd[1] = f2tff(v.y); vd[2] = f2tff(v.z); vd[3] = f2tff(v.w);
    }
    __syncthreads();

    // ---- scores = (Q/8) @ K^T : 128x128. warps 2(M)x4(N) ----
    {
        int wm = wid >> 2, wn = wid & 3;
        float acc[4][4][4];
        #pragma unroll
        for (int i = 0; i < 4; i++)
            #pragma unroll
            for (int j = 0; j < 4; j++)
                #pragma unroll
                for (int q = 0; q < 4; q++) acc[i][j][q] = 0.f;

        const unsigned* Qu = (const unsigned*)Qs;
        const unsigned* Ku = (const unsigned*)Ks;
        #pragma unroll
        for (int ks = 0; ks < 8; ks++) {
            int c = ks*8 + t;
            unsigned a[4][4], bf[4][2];
            #pragma unroll
            for (int i = 0; i < 4; i++) {
                int r = wm*64 + i*16 + g;
                a[i][0] = Qu[r*QS + c];
                a[i][1] = Qu[(r+8)*QS + c];
                a[i][2] = Qu[r*QS + c + 4];
                a[i][3] = Qu[(r+8)*QS + c + 4];
            }
            #pragma unroll
            for (int j = 0; j < 4; j++) {
                int n = wn*32 + j*8 + g;
                bf[j][0] = Ku[n*QS + c];
                bf[j][1] = Ku[n*QS + c + 4];
            }
            #pragma unroll
            for (int i = 0; i < 4; i++)
                #pragma unroll
                for (int j = 0; j < 4; j++)
                    mma8(acc[i][j], a[i], bf[j]);
        }
        #pragma unroll
        for (int i = 0; i < 4; i++) {
            int r0 = wm*64 + i*16 + g;
            #pragma unroll
            for (int j = 0; j < 4; j++) {
                int c = wn*32 + j*8 + 2*t;
                *(float2*)&Ps[r0*PS + c]     = make_float2(acc[i][j][0], acc[i][j][1]);
                *(float2*)&Ps[(r0+8)*PS + c] = make_float2(acc[i][j][2], acc[i][j][3]);
            }
        }
    }
    __syncthreads();

    // ---- softmax: 2 threads per row ----
    {
        int row = tid >> 1;
        float* p = Ps + row*PS + (tid & 1) * 64;
        float mx = -1e30f;
        #pragma unroll 8
        for (int j = 0; j < 64; j++) mx = fmaxf(mx, p[j]);
        mx = fmaxf(mx, __shfl_xor_sync(0xffffffffu, mx, 1));
        float s = 0.f;
        #pragma unroll 8
        for (int j = 0; j < 64; j++) { float e = __expf(p[j] - mx); p[j] = e; s += e; }
        s += __shfl_xor_sync(0xffffffffu, s, 1);
        float inv = 1.f / s;
        #pragma unroll 8
        for (int j = 0; j < 64; j++) p[j] = f2tff(p[j] * inv);
    }
    __syncthreads();

    // ---- O = P @ V, fused residual (from y + prev stats) + stats. warps 4(M)x2(N) ----
    {
        int wm = wid >> 1, wn = wid & 1;
        float acc[2][4][4];
        #pragma unroll
        for (int i = 0; i < 2; i++)
            #pragma unroll
            for (int j = 0; j < 4; j++)
                #pragma unroll
                for (int q = 0; q < 4; q++) acc[i][j][q] = 0.f;

        const unsigned* Pu = (const unsigned*)Ps;
        const unsigned* Vu = (const unsigned*)Vs;
        #pragma unroll
        for (int ks = 0; ks < 16; ks++) {
            int c = ks*8 + t;
            unsigned a[2][4], bf[4][2];
            #pragma unroll
            for (int i = 0; i < 2; i++) {
                int r = wm*32 + i*16 + g;
                a[i][0] = Pu[r*PS + c];
                a[i][1] = Pu[(r+8)*PS + c];
                a[i][2] = Pu[r*PS + c + 4];
                a[i][3] = Pu[(r+8)*PS + c + 4];
            }
            #pragma unroll
            for (int j = 0; j < 4; j++) {
                int n = wn*32 + j*8 + g;
                bf[j][0] = Vu[c*QS + n];
                bf[j][1] = Vu[(c+4)*QS + n];
            }
            #pragma unroll
            for (int i = 0; i < 2; i++)
                #pragma unroll
                for (int j = 0; j < 4; j++)
                    mma8(acc[i][j], a[i], bf[j]);
        }

        float mu = g_mu[b], inv = g_inv[b];
        float* og = g_y + (size_t)b * Tn * Cn + (size_t)h * DHn;
        float s = 0.f, s2 = 0.f;
        #pragma unroll
        for (int i = 0; i < 2; i++) {
            int r0 = wm*32 + i*16 + g;
            #pragma unroll
            for (int j = 0; j < 4; j++) {
                int c = wn*32 + j*8 + 2*t;
                float2 x0 = *(const float2*)&og[(size_t)r0*Cn + c];
                float2 x1 = *(const float2*)&og[(size_t)(r0+8)*Cn + c];
                float v0 = acc[i][j][0] + (x0.x - mu) * inv;
                float v1 = acc[i][j][1] + (x0.y - mu) * inv;
                float v2 = acc[i][j][2] + (x1.x - mu) * inv;
                float v3 = acc[i][j][3] + (x1.y - mu) * inv;
                s  += v0 + v1 + v2 + v3;
                s2 += v0*v0 + v1*v1 + v2*v2 + v3*v3;
                *(float2*)&og[(size_t)r0*Cn + c]     = make_float2(v0, v1);
                *(float2*)&og[(size_t)(r0+8)*Cn + c] = make_float2(v2, v3);
            }
        }

        __shared__ float rs[8], rs2[8];
        #pragma unroll
        for (int o = 16; o > 0; o >>= 1) {
            s  += __shfl_xor_sync(0xffffffffu, s, o);
            s2 += __shfl_xor_sync(0xffffffffu, s2, o);
        }
        if (lane == 0) { rs[wid] = s; rs2[wid] = s2; }
        __syncthreads();
        if (tid == 0) {
            float ts = 0.f, ts2 = 0.f;
            #pragma unroll
            for (int i = 0; i < 8; i++) { ts += rs[i]; ts2 += rs2[i]; }
            g_ps[b*8 + h] = ts; g_ps2[b*8 + h] = ts2;
        }
    }
}

// --------- LN: slots -> (mu,inv); y -> xt (tf32), optional fp32 out -------------------
__global__ __launch_bounds__(256) void ln_norm_kernel(float* __restrict__ xout, int nslots)
{
    int b = blockIdx.y, chunk = blockIdx.x;
    float s = 0.f, s2 = 0.f;
    for (int i = 0; i < nslots; i++) { s += g_ps[b*8 + i]; s2 += g_ps2[b*8 + i]; }
    const float invN = 1.f / (Tn * Cn);
    float mu  = s * invN;
    float var = s2 * invN - mu * mu;
    float inv = rsqrtf(var + 1e-5f);
    if (chunk == 0 && threadIdx.x == 0) { g_mu[b] = mu; g_inv[b] = inv; }

    size_t base4 = ((size_t)b * Tn * Cn + (size_t)chunk * (Tn * Cn / 8)) / 4;
    const float4* y4 = (const float4*)g_y + base4;
    float4* xt4 = (float4*)g_xt + base4;
    const int n4 = Tn * Cn / 8 / 4;
    int tid = threadIdx.x;
    if (xout) {
        float4* x4 = (float4*)xout + base4;
        for (int i = tid; i < n4; i += 256) {
            float4 a = y4[i];
            a.x = (a.x - mu) * inv; a.y = (a.y - mu) * inv;
            a.z = (a.z - mu) * inv; a.w = (a.w - mu) * inv;
            x4[i] = a;
            float4 tv;
            tv.x = f2tff(a.x); tv.y = f2tff(a.y); tv.z = f2tff(a.z); tv.w = f2tff(a.w);
            xt4[i] = tv;
        }
    } else {
        for (int i = tid; i < n4; i += 256) {
            float4 a = y4[i];
            float4 tv;
            tv.x = f2tff((a.x - mu) * inv); tv.y = f2tff((a.y - mu) * inv);
            tv.z = f2tff((a.z - mu) * inv); tv.w = f2tff((a.w - mu) * inv);
            xt4[i] = tv;
        }
    }
}

// ---------------- driver ----------------
extern "C" void kernel_launch(void* const* d_in, const int* in_sizes, int n_in,
                              void* d_out, int out_size)
{
    const float* x     = (const float*)d_in[0];
    const float* enc   = (const float*)d_in[1];
    const float* sa_wq = (const float*)d_in[2];  const float* sa_bq = (const float*)d_in[3];
    const float* sa_wk = (const float*)d_in[4];  const float* sa_bk = (const float*)d_in[5];
    const float* sa_wv = (const float*)d_in[6];  const float* sa_bv = (const float*)d_in[7];
    const float* ca_wq = (const float*)d_in[8];  const float* ca_bq = (const float*)d_in[9];
    const float* ca_wk = (const float*)d_in[10]; const float* ca_bk = (const float*)d_in[11];
    const float* ca_wv = (const float*)d_in[12]; const float* ca_bv = (const float*)d_in[13];
    const float* ff_w1 = (const float*)d_in[14]; const float* ff_b1 = (const float*)d_in[15];
    const float* ff_w2 = (const float*)d_in[16]; const float* ff_b2 = (const float*)d_in[17];
    float* out = (float*)d_out;

    cudaFuncSetAttribute(attn_kernel, cudaFuncAttributeMaxDynamicSharedMemorySize, ATTN_SMEM);
    cudaFuncSetAttribute(gemm_qkv_kernel, cudaFuncAttributeMaxDynamicSharedMemorySize, GEMM_SMEM);
    cudaFuncSetAttribute(gemm_ff1_kernel, cudaFuncAttributeMaxDynamicSharedMemorySize, GEMM_SMEM);
    cudaFuncSetAttribute(gemm_ff2_kernel, cudaFuncAttributeMaxDynamicSharedMemorySize, GEMM_SMEM);

    float *wsaq, *wsak, *wsav, *wcaq, *wcak, *wcav, *wff1, *wff2, *xt, *enct, *yb;
    cudaGetSymbolAddress((void**)&wsaq, g_wsaq);
    cudaGetSymbolAddress((void**)&wsak, g_wsak);
    cudaGetSymbolAddress((void**)&wsav, g_wsav);
    cudaGetSymbolAddress((void**)&wcaq, g_wcaq);
    cudaGetSymbolAddress((void**)&wcak, g_wcak);
    cudaGetSymbolAddress((void**)&wcav, g_wcav);
    cudaGetSymbolAddress((void**)&wff1, g_wff1);
    cudaGetSymbolAddress((void**)&wff2, g_wff2);
    cudaGetSymbolAddress((void**)&xt,   g_xt);
    cudaGetSymbolAddress((void**)&enct, g_enct);
    cudaGetSymbolAddress((void**)&yb,   g_y);

    const int nAct = Bn * Tn * Cn;
    cudaMemcpyAsync(yb, x, sizeof(float) * nAct, cudaMemcpyDeviceToDevice);
    init_stats_kernel<<<1, 64>>>();
    cvt_kernel<<<(nAct + 255) / 256, 256>>>(x, xt, nAct);
    cvt_kernel<<<(nAct + 255) / 256, 256>>>(enc, enct, nAct);
    const int nQW = Ln * Hn * Cn * DHn;
    cvt_qkvw_kernel<<<nQW / 256, 256>>>(sa_wq, wsaq);
    cvt_qkvw_kernel<<<nQW / 256, 256>>>(sa_wk, wsak);
    cvt_qkvw_kernel<<<nQW / 256, 256>>>(sa_wv, wsav);
    cvt_qkvw_kernel<<<nQW / 256, 256>>>(ca_wq, wcaq);
    cvt_qkvw_kernel<<<nQW / 256, 256>>>(ca_wk, wcak);
    cvt_qkvw_kernel<<<nQW / 256, 256>>>(ca_wv, wcav);
    const int nFW = Ln * Cn * FFn;
    cvt_kernel<<<(nFW + 255) / 256, 256>>>(ff_w1, wff1, nFW);
    cvt_kernel<<<(nFW + 255) / 256, 256>>>(ff_w2, wff2, nFW);

    const size_t WSTRIDE = (size_t)Cn * 512;
    const size_t BSTRIDE = (size_t)Hn * DHn;

    for (int l = 0; l < Ln; l++) {
        // ---- self attention ----
        gemm_qkv_kernel<<<dim3(2, 64, 3), 256, GEMM_SMEM>>>(xt, xt,
            wsaq + l * WSTRIDE, wsak + l * WSTRIDE, wsav + l * WSTRIDE,
            sa_bq + l * BSTRIDE, sa_bk + l * BSTRIDE, sa_bv + l * BSTRIDE);
        attn_kernel<<<Bn * Hn, 256, ATTN_SMEM>>>();
        ln_norm_kernel<<<dim3(8, Bn), 256>>>(nullptr, 8);

        // ---- cross attention ----
        gemm_qkv_kernel<<<dim3(2, 64, 3), 256, GEMM_SMEM>>>(xt, enct,
            wcaq + l * WSTRIDE, wcak + l * WSTRIDE, wcav + l * WSTRIDE,
            ca_bq + l * BSTRIDE, ca_bk + l * BSTRIDE, ca_bv + l * BSTRIDE);
        attn_kernel<<<Bn * Hn, 256, ATTN_SMEM>>>();
        ln_norm_kernel<<<dim3(8, Bn), 256>>>(nullptr, 8);

        // ---- feed forward ----
        gemm_ff1_kernel<<<dim3(FFn / 256, (Bn * Tn) / 128), 256, GEMM_SMEM>>>(
            xt, wff1 + (size_t)l * Cn * FFn, ff_b1 + (size_t)l * FFn);
        gemm_ff2_kernel<<<dim3(Cn / 256, (Bn * Tn) / 128), 256, GEMM_SMEM>>>(
            wff2 + (size_t)l * FFn * Cn, ff_b2 + (size_t)l * Cn);
        // FF2 has only Cn/256 = 2 column tiles -> 2 stat slots per batch (R7 fix)
        ln_norm_kernel<<<dim3(8, Bn), 256>>>((l == Ln - 1) ? out : nullptr, 2);
    }
}

// round 11
// speedup vs baseline: 1.0692x; 1.0692x over previous
#include <cuda_runtime.h>

#define Bn 64
#define Tn 128
#define Sn 128
#define Cn 512
#define Hn 8
#define DHn 64
#define FFn 2048
#define Ln 6

// ---------------- scratch (device globals; no allocation allowed) ----------------
__device__ float g_q[Bn*Tn*Cn];          // [B*T, H*DH]
__device__ float g_k[Bn*Sn*Cn];
__device__ float g_v[Bn*Sn*Cn];
__device__ float g_y[Bn*Tn*Cn];          // pre-norm y = x + residual
__device__ float g_h[(size_t)Bn*Tn*FFn]; // FF hidden (tf32-rounded)
__device__ float g_xt[Bn*Tn*Cn];         // tf32 mirror of normalized x
__device__ float g_enct[Bn*Sn*Cn];       // tf32 mirror of encoder output
__device__ float g_ps[Bn*8], g_ps2[Bn*8];// LN partial stats (slots)
__device__ float g_mu[Bn], g_inv[Bn];    // committed LN stats of previous stage
__device__ float g_wsaq[Ln*Cn*Cn], g_wsak[Ln*Cn*Cn], g_wsav[Ln*Cn*Cn];
__device__ float g_wcaq[Ln*Cn*Cn], g_wcak[Ln*Cn*Cn], g_wcav[Ln*Cn*Cn];
__device__ float g_wff1[(size_t)Ln*Cn*FFn];
__device__ float g_wff2[(size_t)Ln*FFn*Cn];

// ---------------- tf32 helpers ----------------
__device__ __forceinline__ unsigned f2tf(float f) {
    unsigned u;
    asm("cvt.rna.tf32.f32 %0, %1;" : "=r"(u) : "f"(f));
    return u;
}
__device__ __forceinline__ float f2tff(float f) { return __uint_as_float(f2tf(f)); }
__device__ __forceinline__ void mma8(float c[4], const unsigned a[4], const unsigned b[2]) {
    asm volatile("mma.sync.aligned.m16n8k8.row.col.f32.tf32.tf32.f32 "
        "{%0,%1,%2,%3}, {%4,%5,%6,%7}, {%8,%9}, {%0,%1,%2,%3};"
        : "+f"(c[0]), "+f"(c[1]), "+f"(c[2]), "+f"(c[3])
        : "r"(a[0]), "r"(a[1]), "r"(a[2]), "r"(a[3]), "r"(b[0]), "r"(b[1]));
}
__device__ __forceinline__ void cpasync16(void* s, const void* g) {
    unsigned sa = (unsigned)__cvta_generic_to_shared(s);
    asm volatile("cp.async.cg.shared.global [%0], [%1], 16;" :: "r"(sa), "l"(g));
}

// ---------------- conversion kernels (once per launch) ----------------
__global__ void cvt_kernel(const float* __restrict__ src, float* __restrict__ dst, int n) {
    int i = blockIdx.x * 256 + threadIdx.x;
    if (i < n) dst[i] = f2tff(src[i]);
}
// src [L,H,C,DH] -> dst [L,C,H*DH] with tf32 rounding
__global__ void cvt_qkvw_kernel(const float* __restrict__ src, float* __restrict__ dst) {
    int i = blockIdx.x * 256 + threadIdx.x;
    int d = i & 63, c = (i >> 6) & 511, h = (i >> 15) & 7, l = i >> 18;
    dst[((size_t)(l * Cn + c)) * 512 + h * 64 + d] = f2tff(src[i]);
}
__global__ void init_stats_kernel() {
    int i = threadIdx.x;
    if (i < Bn) { g_mu[i] = 0.f; g_inv[i] = 1.f; }
}

// ------ unified tf32 GEMM: block 128x128, warp 64x32, 3-stage cp.async ----------------
// Physical-k permutation: logical mma k-lane (t, t+4) <-> physical columns (2t, 2t+1),
// applied identically to A and B fragments (bijective per k8 group -> identical sum).
// A frag: conflict-free LDS.64 (ASTR=40 -> double-bank 4g+t distinct per 16-lane phase).
// B frag: conflict-free LDS.32 (BSTR=132 == 4 mod 16 -> banks 8t+g+const all distinct).
#define ASTR 40
#define BSTR 132
#define ABUF (128*ASTR)
#define BBUF (32*BSTR)
#define NSTG 3
#define GEMM_SMEM ((NSTG*(ABUF+BBUF)) * (int)sizeof(float))   // 112128 B

// EPI: 0 = bias only, 1 = relu + tf32 round, 2 = residual-from-y add + LN partial stats
template<int EPI>
__device__ __forceinline__ void gemm_core(
    const float* __restrict__ A, const float* __restrict__ W,
    const float* __restrict__ bias, float* __restrict__ outp,
    const float* __restrict__ resid,
    int N, int K, int rowTile, int colTile, float* smem)
{
    float* As = smem;
    float* Bs = smem + NSTG * ABUF;

    int tid = threadIdx.x, wid = tid >> 5, lane = tid & 31;
    int wm = wid >> 2, wn = wid & 3;        // 2(M) x 4(N) warps, warp 64x32
    int g = lane >> 2, t = lane & 3;

    float acc[4][4][4];
    #pragma unroll
    for (int i = 0; i < 4; i++)
        #pragma unroll
        for (int j = 0; j < 4; j++)
            #pragma unroll
            for (int q = 0; q < 4; q++) acc[i][j][q] = 0.f;

    const float* Ab = A + (size_t)rowTile * K;
    const float* Wb = W + colTile;
    int KT = K >> 5;

    // prologue: stage slabs 0, 1
    #pragma unroll
    for (int st = 0; st < 2; st++) {
        int k0 = st << 5;
        float* Ad = As + st * ABUF;
        float* Bd = Bs + st * BBUF;
        #pragma unroll
        for (int j = 0; j < 4; j++) {       // A: 128x32 = 1024 float4
            int q = tid + j * 256; int r = q >> 3, ko = (q & 7) * 4;
            cpasync16(&Ad[r * ASTR + ko], &Ab[(size_t)r * K + k0 + ko]);
        }
        #pragma unroll
        for (int j = 0; j < 4; j++) {       // B: 32x128 = 1024 float4
            int q = tid + j * 256; int kk = q >> 5, no = (q & 31) * 4;
            cpasync16(&Bd[kk * BSTR + no], &Wb[(size_t)(k0 + kk) * N + no]);
        }
        asm volatile("cp.async.commit_group;");
    }

    int buf = 0;
    for (int kt = 0; kt < KT; kt++) {
        asm volatile("cp.async.wait_group 1;");
        __syncthreads();

        const float* Af = As + buf * ABUF;
        const unsigned* Bu = (const unsigned*)(Bs + buf * BBUF);
        #pragma unroll
        for (int ks = 0; ks < 4; ks++) {
            int c0 = ks * 8 + 2 * t;            // physical column pair (c0, c0+1)
            unsigned a[4][4], bf[4][2];
            #pragma unroll
            for (int i = 0; i < 4; i++) {
                int r = wm * 64 + i * 16 + g;
                float2 p0 = *(const float2*)&Af[r * ASTR + c0];
                float2 p1 = *(const float2*)&Af[(r + 8) * ASTR + c0];
                a[i][0] = __float_as_uint(p0.x);   // logical k = t
                a[i][2] = __float_as_uint(p0.y);   // logical k = t+4
                a[i][1] = __float_as_uint(p1.x);
                a[i][3] = __float_as_uint(p1.y);
            }
            #pragma unroll
            for (int j = 0; j < 4; j++) {
                int n = wn * 32 + j * 8 + g;
                bf[j][0] = Bu[c0 * BSTR + n];          // logical k = t
                bf[j][1] = Bu[(c0 + 1) * BSTR + n];    // logical k = t+4
            }
            #pragma unroll
            for (int i = 0; i < 4; i++)
                #pragma unroll
                for (int j = 0; j < 4; j++)
                    mma8(acc[i][j], a[i], bf[j]);
        }

        // prefetch slab kt+2 into the free buffer
        if (kt + 2 < KT) {
            int k0 = (kt + 2) << 5;
            int nb = kt + 2; nb -= (nb / NSTG) * NSTG;
            float* Ad = As + nb * ABUF;
            float* Bd = Bs + nb * BBUF;
            #pragma unroll
            for (int j = 0; j < 4; j++) {
                int q = tid + j * 256; int r = q >> 3, ko = (q & 7) * 4;
                cpasync16(&Ad[r * ASTR + ko], &Ab[(size_t)r * K + k0 + ko]);
            }
            #pragma unroll
            for (int j = 0; j < 4; j++) {
                int q = tid + j * 256; int kk = q >> 5, no = (q & 31) * 4;
                cpasync16(&Bd[kk * BSTR + no], &Wb[(size_t)(k0 + kk) * N + no]);
            }
        }
        asm volatile("cp.async.commit_group;");

        buf++; if (buf == NSTG) buf = 0;
    }

    float s = 0.f, s2 = 0.f;
    float mu = 0.f, inv = 1.f;
    if (EPI == 2) { mu = g_mu[rowTile >> 7]; inv = g_inv[rowTile >> 7]; }
    #pragma unroll
    for (int i = 0; i < 4; i++) {
        int r0 = rowTile + wm * 64 + i * 16 + g;
        #pragma unroll
        for (int j = 0; j < 4; j++) {
            int c = colTile + wn * 32 + j * 8 + 2 * t;
            float b0 = bias[c], b1 = bias[c + 1];
            float v0 = acc[i][j][0] + b0, v1 = acc[i][j][1] + b1;
            float v2 = acc[i][j][2] + b0, v3 = acc[i][j][3] + b1;
            if (EPI == 1) {
                v0 = f2tff(fmaxf(v0, 0.f)); v1 = f2tff(fmaxf(v1, 0.f));
                v2 = f2tff(fmaxf(v2, 0.f)); v3 = f2tff(fmaxf(v3, 0.f));
            }
            if (EPI == 2) {
                float2 x0 = *(const float2*)&resid[(size_t)r0 * N + c];
                float2 x1 = *(const float2*)&resid[(size_t)(r0 + 8) * N + c];
                v0 += (x0.x - mu) * inv; v1 += (x0.y - mu) * inv;
                v2 += (x1.x - mu) * inv; v3 += (x1.y - mu) * inv;
                s  += v0 + v1 + v2 + v3;
                s2 += v0*v0 + v1*v1 + v2*v2 + v3*v3;
            }
            *(float2*)&outp[(size_t)r0 * N + c]       = make_float2(v0, v1);
            *(float2*)&outp[(size_t)(r0 + 8) * N + c] = make_float2(v2, v3);
        }
    }

    if (EPI == 2) {
        __shared__ float rs[8], rs2[8];
        #pragma unroll
        for (int o = 16; o > 0; o >>= 1) {
            s  += __shfl_xor_sync(0xffffffffu, s, o);
            s2 += __shfl_xor_sync(0xffffffffu, s2, o);
        }
        if (lane == 0) { rs[wid] = s; rs2[wid] = s2; }
        __syncthreads();
        if (tid == 0) {
            float ts = 0.f, ts2 = 0.f;
            #pragma unroll
            for (int i = 0; i < 8; i++) { ts += rs[i]; ts2 += rs2[i]; }
            int slot = (rowTile >> 7) * 8 + (colTile >> 7);
            g_ps[slot] = ts; g_ps2[slot] = ts2;
        }
    }
}

__global__ __launch_bounds__(256, 2) void gemm_qkv_kernel(
    const float* __restrict__ Aq, const float* __restrict__ Akv,
    const float* __restrict__ wq, const float* __restrict__ wk, const float* __restrict__ wv,
    const float* __restrict__ bq, const float* __restrict__ bk, const float* __restrict__ bv)
{
    extern __shared__ float smem[];
    const float* A; const float* W; const float* bias; float* outp;
    int z = blockIdx.z;
    if (z == 0)      { A = Aq;  W = wq; bias = bq; outp = g_q; }
    else if (z == 1) { A = Akv; W = wk; bias = bk; outp = g_k; }
    else             { A = Akv; W = wv; bias = bv; outp = g_v; }
    gemm_core<0>(A, W, bias, outp, nullptr, 512, 512,
                 blockIdx.y * 128, blockIdx.x * 128, smem);
}

__global__ __launch_bounds__(256, 2) void gemm_ff1_kernel(
    const float* __restrict__ A, const float* __restrict__ W,
    const float* __restrict__ bias)
{
    extern __shared__ float smem[];
    gemm_core<1>(A, W, bias, g_h, nullptr, FFn, Cn,
                 blockIdx.y * 128, blockIdx.x * 128, smem);
}
__global__ __launch_bounds__(256, 2) void gemm_ff2_kernel(
    const float* __restrict__ W, const float* __restrict__ bias)
{
    extern __shared__ float smem[];
    gemm_core<2>(g_h, W, bias, g_y, g_y, Cn, FFn,
                 blockIdx.y * 128, blockIdx.x * 128, smem);
}

// ---------------- fused attention per (b,h) + residual-from-y add + LN stats ----------
#define QS 68
#define PS 132
#define ATTN_SMEM ((3*128*QS + 128*PS) * (int)sizeof(float))   // 172032 B

__global__ __launch_bounds__(256) void attn_kernel()
{
    extern __shared__ float sm[];
    float* Qs = sm;
    float* Ks = sm + 128*QS;
    float* Vs = sm + 2*128*QS;
    float* Ps = sm + 3*128*QS;

    int bh = blockIdx.x;
    int h = bh & (Hn - 1);
    int b = bh >> 3;
    int tid = threadIdx.x, wid = tid >> 5, lane = tid & 31;
    int g = lane >> 2, t = lane & 3;

    const float* qg = g_q + (size_t)b * Tn * Cn + h * DHn;
    const float* kg = g_k + (size_t)b * Sn * Cn + h * DHn;
    const float* vg = g_v + (size_t)b * Sn * Cn + h * DHn;

    for (int e = tid; e < Tn * DHn / 4; e += 256) {
        int r = e >> 4, d = (e & 15) * 4;
        size_t gi = (size_t)r * Cn + d;
        float4 q = *(const float4*)&qg[gi];
        float4 k = *(const float4*)&kg[gi];
        float4 v = *(const float4*)&vg[gi];
        float* qd = &Qs[r*QS + d];
        qd[0] = f2tff(q.x * 0.125f); qd[1] = f2tff(q.y * 0.125f);
        qd[2] = f2tff(q.z * 0.125f); qd[3] = f2tff(q.w * 0.125f);
        float* kd = &Ks[r*QS + d];
        kd[0] = f2tff(k.x); kd[1] = f2tff(k.y); kd[2] = f2tff(k.z); kd[3] = f2tff(k.w);
        float* vd = &Vs[r*QS + d];
        vd[0] = f2tff(v.x); vd[1] = f2tff(v.y); vd[2] = f2tff(v.z); vd[3] = f2tff(v.w);
    }
    __syncthreads();

    // ---- scores = (Q/8) @ K^T : 128x128. warps 2(M)x4(N) ----
    {
        int wm = wid >> 2, wn = wid & 3;
        float acc[4][4][4];
        #pragma unroll
        for (int i = 0; i < 4; i++)
            #pragma unroll
            for (int j = 0; j < 4; j++)
                #pragma unroll
                for (int q = 0; q < 4; q++) acc[i][j][q] = 0.f;

        const unsigned* Qu = (const unsigned*)Qs;
        const unsigned* Ku = (const unsigned*)Ks;
        #pragma unroll
        for (int ks = 0; ks < 8; ks++) {
            int c = ks*8 + t;
            unsigned a[4][4], bf[4][2];
            #pragma unroll
            for (int i = 0; i < 4; i++) {
                int r = wm*64 + i*16 + g;
                a[i][0] = Qu[r*QS + c];
                a[i][1] = Qu[(r+8)*QS + c];
                a[i][2] = Qu[r*QS + c + 4];
                a[i][3] = Qu[(r+8)*QS + c + 4];
            }
            #pragma unroll
            for (int j = 0; j < 4; j++) {
                int n = wn*32 + j*8 + g;
                bf[j][0] = Ku[n*QS + c];
                bf[j][1] = Ku[n*QS + c + 4];
            }
            #pragma unroll
            for (int i = 0; i < 4; i++)
                #pragma unroll
                for (int j = 0; j < 4; j++)
                    mma8(acc[i][j], a[i], bf[j]);
        }
        #pragma unroll
        for (int i = 0; i < 4; i++) {
            int r0 = wm*64 + i*16 + g;
            #pragma unroll
            for (int j = 0; j < 4; j++) {
                int c = wn*32 + j*8 + 2*t;
                *(float2*)&Ps[r0*PS + c]     = make_float2(acc[i][j][0], acc[i][j][1]);
                *(float2*)&Ps[(r0+8)*PS + c] = make_float2(acc[i][j][2], acc[i][j][3]);
            }
        }
    }
    __syncthreads();

    // ---- softmax: 2 threads per row ----
    {
        int row = tid >> 1;
        float* p = Ps + row*PS + (tid & 1) * 64;
        float mx = -1e30f;
        #pragma unroll 8
        for (int j = 0; j < 64; j++) mx = fmaxf(mx, p[j]);
        mx = fmaxf(mx, __shfl_xor_sync(0xffffffffu, mx, 1));
        float s = 0.f;
        #pragma unroll 8
        for (int j = 0; j < 64; j++) { float e = __expf(p[j] - mx); p[j] = e; s += e; }
        s += __shfl_xor_sync(0xffffffffu, s, 1);
        float inv = 1.f / s;
        #pragma unroll 8
        for (int j = 0; j < 64; j++) p[j] = f2tff(p[j] * inv);
    }
    __syncthreads();

    // ---- O = P @ V, fused residual (from y + prev stats) + stats. warps 4(M)x2(N) ----
    {
        int wm = wid >> 1, wn = wid & 1;
        float acc[2][4][4];
        #pragma unroll
        for (int i = 0; i < 2; i++)
            #pragma unroll
            for (int j = 0; j < 4; j++)
                #pragma unroll
                for (int q = 0; q < 4; q++) acc[i][j][q] = 0.f;

        const unsigned* Pu = (const unsigned*)Ps;
        const unsigned* Vu = (const unsigned*)Vs;
        #pragma unroll
        for (int ks = 0; ks < 16; ks++) {
            int c = ks*8 + t;
            unsigned a[2][4], bf[4][2];
            #pragma unroll
            for (int i = 0; i < 2; i++) {
                int r = wm*32 + i*16 + g;
                a[i][0] = Pu[r*PS + c];
                a[i][1] = Pu[(r+8)*PS + c];
                a[i][2] = Pu[r*PS + c + 4];
                a[i][3] = Pu[(r+8)*PS + c + 4];
            }
            #pragma unroll
            for (int j = 0; j < 4; j++) {
                int n = wn*32 + j*8 + g;
                bf[j][0] = Vu[c*QS + n];
                bf[j][1] = Vu[(c+4)*QS + n];
            }
            #pragma unroll
            for (int i = 0; i < 2; i++)
                #pragma unroll
                for (int j = 0; j < 4; j++)
                    mma8(acc[i][j], a[i], bf[j]);
        }

        float mu = g_mu[b], inv = g_inv[b];
        float* og = g_y + (size_t)b * Tn * Cn + (size_t)h * DHn;
        float s = 0.f, s2 = 0.f;
        #pragma unroll
        for (int i = 0; i < 2; i++) {
            int r0 = wm*32 + i*16 + g;
            #pragma unroll
            for (int j = 0; j < 4; j++) {
                int c = wn*32 + j*8 + 2*t;
                float2 x0 = *(const float2*)&og[(size_t)r0*Cn + c];
                float2 x1 = *(const float2*)&og[(size_t)(r0+8)*Cn + c];
                float v0 = acc[i][j][0] + (x0.x - mu) * inv;
                float v1 = acc[i][j][1] + (x0.y - mu) * inv;
                float v2 = acc[i][j][2] + (x1.x - mu) * inv;
                float v3 = acc[i][j][3] + (x1.y - mu) * inv;
                s  += v0 + v1 + v2 + v3;
                s2 += v0*v0 + v1*v1 + v2*v2 + v3*v3;
                *(float2*)&og[(size_t)r0*Cn + c]     = make_float2(v0, v1);
                *(float2*)&og[(size_t)(r0+8)*Cn + c] = make_float2(v2, v3);
            }
        }

        __shared__ float rs[8], rs2[8];
        #pragma unroll
        for (int o = 16; o > 0; o >>= 1) {
            s  += __shfl_xor_sync(0xffffffffu, s, o);
            s2 += __shfl_xor_sync(0xffffffffu, s2, o);
        }
        if (lane == 0) { rs[wid] = s; rs2[wid] = s2; }
        __syncthreads();
        if (tid == 0) {
            float ts = 0.f, ts2 = 0.f;
            #pragma unroll
            for (int i = 0; i < 8; i++) { ts += rs[i]; ts2 += rs2[i]; }
            g_ps[b*8 + h] = ts; g_ps2[b*8 + h] = ts2;
        }
    }
}

// --------- LN: slots -> (mu,inv); y -> xt (tf32), optional fp32 out -------------------
__global__ __launch_bounds__(256) void ln_norm_kernel(float* __restrict__ xout, int nslots)
{
    int b = blockIdx.y, chunk = blockIdx.x;
    float s = 0.f, s2 = 0.f;
    for (int i = 0; i < nslots; i++) { s += g_ps[b*8 + i]; s2 += g_ps2[b*8 + i]; }
    const float invN = 1.f / (Tn * Cn);
    float mu  = s * invN;
    float var = s2 * invN - mu * mu;
    float inv = rsqrtf(var + 1e-5f);
    if (chunk == 0 && threadIdx.x == 0) { g_mu[b] = mu; g_inv[b] = inv; }

    size_t base4 = ((size_t)b * Tn * Cn + (size_t)chunk * (Tn * Cn / 8)) / 4;
    const float4* y4 = (const float4*)g_y + base4;
    float4* xt4 = (float4*)g_xt + base4;
    const int n4 = Tn * Cn / 8 / 4;
    int tid = threadIdx.x;
    if (xout) {
        float4* x4 = (float4*)xout + base4;
        for (int i = tid; i < n4; i += 256) {
            float4 a = y4[i];
            a.x = (a.x - mu) * inv; a.y = (a.y - mu) * inv;
            a.z = (a.z - mu) * inv; a.w = (a.w - mu) * inv;
            x4[i] = a;
            float4 tv;
            tv.x = f2tff(a.x); tv.y = f2tff(a.y); tv.z = f2tff(a.z); tv.w = f2tff(a.w);
            xt4[i] = tv;
        }
    } else {
        for (int i = tid; i < n4; i += 256) {
            float4 a = y4[i];
            float4 tv;
            tv.x = f2tff((a.x - mu) * inv); tv.y = f2tff((a.y - mu) * inv);
            tv.z = f2tff((a.z - mu) * inv); tv.w = f2tff((a.w - mu) * inv);
            xt4[i] = tv;
        }
    }
}

// ---------------- driver ----------------
extern "C" void kernel_launch(void* const* d_in, const int* in_sizes, int n_in,
                              void* d_out, int out_size)
{
    const float* x     = (const float*)d_in[0];
    const float* enc   = (const float*)d_in[1];
    const float* sa_wq = (const float*)d_in[2];  const float* sa_bq = (const float*)d_in[3];
    const float* sa_wk = (const float*)d_in[4];  const float* sa_bk = (const float*)d_in[5];
    const float* sa_wv = (const float*)d_in[6];  const float* sa_bv = (const float*)d_in[7];
    const float* ca_wq = (const float*)d_in[8];  const float* ca_bq = (const float*)d_in[9];
    const float* ca_wk = (const float*)d_in[10]; const float* ca_bk = (const float*)d_in[11];
    const float* ca_wv = (const float*)d_in[12]; const float* ca_bv = (const float*)d_in[13];
    const float* ff_w1 = (const float*)d_in[14]; const float* ff_b1 = (const float*)d_in[15];
    const float* ff_w2 = (const float*)d_in[16]; const float* ff_b2 = (const float*)d_in[17];
    float* out = (float*)d_out;

    cudaFuncSetAttribute(attn_kernel, cudaFuncAttributeMaxDynamicSharedMemorySize, ATTN_SMEM);
    cudaFuncSetAttribute(gemm_qkv_kernel, cudaFuncAttributeMaxDynamicSharedMemorySize, GEMM_SMEM);
    cudaFuncSetAttribute(gemm_ff1_kernel, cudaFuncAttributeMaxDynamicSharedMemorySize, GEMM_SMEM);
    cudaFuncSetAttribute(gemm_ff2_kernel, cudaFuncAttributeMaxDynamicSharedMemorySize, GEMM_SMEM);

    float *wsaq, *wsak, *wsav, *wcaq, *wcak, *wcav, *wff1, *wff2, *xt, *enct, *yb;
    cudaGetSymbolAddress((void**)&wsaq, g_wsaq);
    cudaGetSymbolAddress((void**)&wsak, g_wsak);
    cudaGetSymbolAddress((void**)&wsav, g_wsav);
    cudaGetSymbolAddress((void**)&wcaq, g_wcaq);
    cudaGetSymbolAddress((void**)&wcak, g_wcak);
    cudaGetSymbolAddress((void**)&wcav, g_wcav);
    cudaGetSymbolAddress((void**)&wff1, g_wff1);
    cudaGetSymbolAddress((void**)&wff2, g_wff2);
    cudaGetSymbolAddress((void**)&xt,   g_xt);
    cudaGetSymbolAddress((void**)&enct, g_enct);
    cudaGetSymbolAddress((void**)&yb,   g_y);

    const int nAct = Bn * Tn * Cn;
    cudaMemcpyAsync(yb, x, sizeof(float) * nAct, cudaMemcpyDeviceToDevice);
    init_stats_kernel<<<1, 64>>>();
    cvt_kernel<<<(nAct + 255) / 256, 256>>>(x, xt, nAct);
    cvt_kernel<<<(nAct + 255) / 256, 256>>>(enc, enct, nAct);
    const int nQW = Ln * Hn * Cn * DHn;
    cvt_qkvw_kernel<<<nQW / 256, 256>>>(sa_wq, wsaq);
    cvt_qkvw_kernel<<<nQW / 256, 256>>>(sa_wk, wsak);
    cvt_qkvw_kernel<<<nQW / 256, 256>>>(sa_wv, wsav);
    cvt_qkvw_kernel<<<nQW / 256, 256>>>(ca_wq, wcaq);
    cvt_qkvw_kernel<<<nQW / 256, 256>>>(ca_wk, wcak);
    cvt_qkvw_kernel<<<nQW / 256, 256>>>(ca_wv, wcav);
    const int nFW = Ln * Cn * FFn;
    cvt_kernel<<<(nFW + 255) / 256, 256>>>(ff_w1, wff1, nFW);
    cvt_kernel<<<(nFW + 255) / 256, 256>>>(ff_w2, wff2, nFW);

    const size_t WSTRIDE = (size_t)Cn * 512;
    const size_t BSTRIDE = (size_t)Hn * DHn;

    for (int l = 0; l < Ln; l++) {
        // ---- self attention ----
        gemm_qkv_kernel<<<dim3(4, 64, 3), 256, GEMM_SMEM>>>(xt, xt,
            wsaq + l * WSTRIDE, wsak + l * WSTRIDE, wsav + l * WSTRIDE,
            sa_bq + l * BSTRIDE, sa_bk + l * BSTRIDE, sa_bv + l * BSTRIDE);
        attn_kernel<<<Bn * Hn, 256, ATTN_SMEM>>>();
        ln_norm_kernel<<<dim3(8, Bn), 256>>>(nullptr, 8);

        // ---- cross attention ----
        gemm_qkv_kernel<<<dim3(4, 64, 3), 256, GEMM_SMEM>>>(xt, enct,
            wcaq + l * WSTRIDE, wcak + l * WSTRIDE, wcav + l * WSTRIDE,
            ca_bq + l * BSTRIDE, ca_bk + l * BSTRIDE, ca_bv + l * BSTRIDE);
        attn_kernel<<<Bn * Hn, 256, ATTN_SMEM>>>();
        ln_norm_kernel<<<dim3(8, Bn), 256>>>(nullptr, 8);

        // ---- feed forward ----
        gemm_ff1_kernel<<<dim3(FFn / 128, (Bn * Tn) / 128), 256, GEMM_SMEM>>>(
            xt, wff1 + (size_t)l * Cn * FFn, ff_b1 + (size_t)l * FFn);
        gemm_ff2_kernel<<<dim3(Cn / 128, (Bn * Tn) / 128), 256, GEMM_SMEM>>>(
            wff2 + (size_t)l * FFn * Cn, ff_b2 + (size_t)l * Cn);
        // FF2 col tiles = Cn/128 = 4 -> 4 stat slots per batch
        ln_norm_kernel<<<dim3(8, Bn), 256>>>((l == Ln - 1) ? out : nullptr, 4);
    }
}

// round 14
// speedup vs baseline: 1.1012x; 1.0299x over previous
#include <cuda_runtime.h>

#define Bn 64
#define Tn 128
#define Sn 128
#define Cn 512
#define Hn 8
#define DHn 64
#define FFn 2048
#define Ln 6

// ---------------- scratch (device globals; no allocation allowed) ----------------
__device__ float g_q[Bn*Tn*Cn];          // [B*T, H*DH]
__device__ float g_k[Bn*Sn*Cn];
__device__ float g_v[Bn*Sn*Cn];
__device__ float g_y[Bn*Tn*Cn];          // pre-norm y = x + residual
__device__ float g_h[(size_t)Bn*Tn*FFn]; // FF hidden (tf32-rounded)
__device__ float g_xt[Bn*Tn*Cn];         // tf32 mirror of normalized x
__device__ float g_enct[Bn*Sn*Cn];       // tf32 mirror of encoder output
__device__ float g_ps[Bn*8], g_ps2[Bn*8];// LN partial stats (slots)
__device__ float g_mu[Bn], g_inv[Bn];    // committed LN stats of previous stage
__device__ float g_wsaq[Ln*Cn*Cn], g_wsak[Ln*Cn*Cn], g_wsav[Ln*Cn*Cn];
__device__ float g_wcaq[Ln*Cn*Cn], g_wcak[Ln*Cn*Cn], g_wcav[Ln*Cn*Cn];
__device__ float g_wff1[(size_t)Ln*Cn*FFn];
__device__ float g_wff2[(size_t)Ln*FFn*Cn];

// ---------------- tf32 helpers ----------------
__device__ __forceinline__ unsigned f2tf(float f) {
    unsigned u;
    asm("cvt.rna.tf32.f32 %0, %1;" : "=r"(u) : "f"(f));
    return u;
}
__device__ __forceinline__ float f2tff(float f) { return __uint_as_float(f2tf(f)); }
__device__ __forceinline__ void mma8(float c[4], const unsigned a[4], const unsigned b[2]) {
    asm volatile("mma.sync.aligned.m16n8k8.row.col.f32.tf32.tf32.f32 "
        "{%0,%1,%2,%3}, {%4,%5,%6,%7}, {%8,%9}, {%0,%1,%2,%3};"
        : "+f"(c[0]), "+f"(c[1]), "+f"(c[2]), "+f"(c[3])
        : "r"(a[0]), "r"(a[1]), "r"(a[2]), "r"(a[3]), "r"(b[0]), "r"(b[1]));
}
__device__ __forceinline__ void cpasync16(void* s, const void* g) {
    unsigned sa = (unsigned)__cvta_generic_to_shared(s);
    asm volatile("cp.async.cg.shared.global [%0], [%1], 16;" :: "r"(sa), "l"(g));
}

// ---------------- conversion kernels (once per launch) ----------------
__global__ void cvt_kernel(const float* __restrict__ src, float* __restrict__ dst, int n) {
    int i = blockIdx.x * 256 + threadIdx.x;
    if (i < n) dst[i] = f2tff(src[i]);
}
// src [L,H,C,DH] -> dst [L,C,H*DH] with tf32 rounding
__global__ void cvt_qkvw_kernel(const float* __restrict__ src, float* __restrict__ dst) {
    int i = blockIdx.x * 256 + threadIdx.x;
    int d = i & 63, c = (i >> 6) & 511, h = (i >> 15) & 7, l = i >> 18;
    dst[((size_t)(l * Cn + c)) * 512 + h * 64 + d] = f2tff(src[i]);
}
__global__ void init_stats_kernel() {
    int i = threadIdx.x;
    if (i < Bn) { g_mu[i] = 0.f; g_inv[i] = 1.f; }
}

// ------ unified tf32 GEMM: block 128x128, warp 64x32, 3-stage cp.async (R5 hot loop) --
#define ASTR 36
#define BSTR 136
#define ABUF (128*ASTR)
#define BBUF (32*BSTR)
#define NSTG 3
#define GEMM_SMEM ((NSTG*(ABUF+BBUF)) * (int)sizeof(float))   // 107520 B

// EPI: 0 = bias only, 1 = relu + tf32 round, 2 = residual-from-y add + LN partial stats
template<int EPI>
__device__ __forceinline__ void gemm_core(
    const float* __restrict__ A, const float* __restrict__ W,
    const float* __restrict__ bias, float* __restrict__ outp,
    const float* __restrict__ resid,
    int N, int K, int rowTile, int colTile, float* smem)
{
    float* As = smem;
    float* Bs = smem + NSTG * ABUF;

    int tid = threadIdx.x, wid = tid >> 5, lane = tid & 31;
    int wm = wid >> 2, wn = wid & 3;        // 2(M) x 4(N) warps, warp 64x32
    int g = lane >> 2, t = lane & 3;

    float acc[4][4][4];
    #pragma unroll
    for (int i = 0; i < 4; i++)
        #pragma unroll
        for (int j = 0; j < 4; j++)
            #pragma unroll
            for (int q = 0; q < 4; q++) acc[i][j][q] = 0.f;

    const float* Ab = A + (size_t)rowTile * K;
    const float* Wb = W + colTile;
    int KT = K >> 5;

    // prologue: stage slabs 0, 1
    #pragma unroll
    for (int st = 0; st < 2; st++) {
        int k0 = st << 5;
        float* Ad = As + st * ABUF;
        float* Bd = Bs + st * BBUF;
        #pragma unroll
        for (int j = 0; j < 4; j++) {       // A: 128x32 = 1024 float4
            int q = tid + j * 256; int r = q >> 3, ko = (q & 7) * 4;
            cpasync16(&Ad[r * ASTR + ko], &Ab[(size_t)r * K + k0 + ko]);
        }
        #pragma unroll
        for (int j = 0; j < 4; j++) {       // B: 32x128 = 1024 float4
            int q = tid + j * 256; int kk = q >> 5, no = (q & 31) * 4;
            cpasync16(&Bd[kk * BSTR + no], &Wb[(size_t)(k0 + kk) * N + no]);
        }
        asm volatile("cp.async.commit_group;");
    }

    int buf = 0;
    for (int kt = 0; kt < KT; kt++) {
        asm volatile("cp.async.wait_group 1;");
        __syncthreads();

        const unsigned* Au = (const unsigned*)(As + buf * ABUF);
        const unsigned* Bu = (const unsigned*)(Bs + buf * BBUF);
        #pragma unroll
        for (int ks = 0; ks < 4; ks++) {
            int c = ks * 8 + t;
            unsigned a[4][4], bf[4][2];
            #pragma unroll
            for (int i = 0; i < 4; i++) {
                int r = wm * 64 + i * 16 + g;
                a[i][0] = Au[r * ASTR + c];
                a[i][1] = Au[(r + 8) * ASTR + c];
                a[i][2] = Au[r * ASTR + c + 4];
                a[i][3] = Au[(r + 8) * ASTR + c + 4];
            }
            #pragma unroll
            for (int j = 0; j < 4; j++) {
                int n = wn * 32 + j * 8 + g;
                bf[j][0] = Bu[c * BSTR + n];
                bf[j][1] = Bu[(c + 4) * BSTR + n];
            }
            #pragma unroll
            for (int i = 0; i < 4; i++)
                #pragma unroll
                for (int j = 0; j < 4; j++)
                    mma8(acc[i][j], a[i], bf[j]);
        }

        // prefetch slab kt+2 into the free buffer
        if (kt + 2 < KT) {
            int k0 = (kt + 2) << 5;
            int nb = kt + 2; nb -= (nb / NSTG) * NSTG;
            float* Ad = As + nb * ABUF;
            float* Bd = Bs + nb * BBUF;
            #pragma unroll
            for (int j = 0; j < 4; j++) {
                int q = tid + j * 256; int r = q >> 3, ko = (q & 7) * 4;
                cpasync16(&Ad[r * ASTR + ko], &Ab[(size_t)r * K + k0 + ko]);
            }
            #pragma unroll
            for (int j = 0; j < 4; j++) {
                int q = tid + j * 256; int kk = q >> 5, no = (q & 31) * 4;
                cpasync16(&Bd[kk * BSTR + no], &Wb[(size_t)(k0 + kk) * N + no]);
            }
        }
        asm volatile("cp.async.commit_group;");

        buf++; if (buf == NSTG) buf = 0;
    }

    float s = 0.f, s2 = 0.f;
    float mu = 0.f, inv = 1.f;
    if (EPI == 2) { mu = g_mu[rowTile >> 7]; inv = g_inv[rowTile >> 7]; }
    #pragma unroll
    for (int i = 0; i < 4; i++) {
        int r0 = rowTile + wm * 64 + i * 16 + g;
        #pragma unroll
        for (int j = 0; j < 4; j++) {
            int c = colTile + wn * 32 + j * 8 + 2 * t;
            float b0 = bias[c], b1 = bias[c + 1];
            float v0 = acc[i][j][0] + b0, v1 = acc[i][j][1] + b1;
            float v2 = acc[i][j][2] + b0, v3 = acc[i][j][3] + b1;
            if (EPI == 1) {
                v0 = f2tff(fmaxf(v0, 0.f)); v1 = f2tff(fmaxf(v1, 0.f));
                v2 = f2tff(fmaxf(v2, 0.f)); v3 = f2tff(fmaxf(v3, 0.f));
            }
            if (EPI == 2) {
                float2 x0 = *(const float2*)&resid[(size_t)r0 * N + c];
                float2 x1 = *(const float2*)&resid[(size_t)(r0 + 8) * N + c];
                v0 += (x0.x - mu) * inv; v1 += (x0.y - mu) * inv;
                v2 += (x1.x - mu) * inv; v3 += (x1.y - mu) * inv;
                s  += v0 + v1 + v2 + v3;
                s2 += v0*v0 + v1*v1 + v2*v2 + v3*v3;
            }
            *(float2*)&outp[(size_t)r0 * N + c]       = make_float2(v0, v1);
            *(float2*)&outp[(size_t)(r0 + 8) * N + c] = make_float2(v2, v3);
        }
    }

    if (EPI == 2) {
        __shared__ float rs[8], rs2[8];
        #pragma unroll
        for (int o = 16; o > 0; o >>= 1) {
            s  += __shfl_xor_sync(0xffffffffu, s, o);
            s2 += __shfl_xor_sync(0xffffffffu, s2, o);
        }
        if (lane == 0) { rs[wid] = s; rs2[wid] = s2; }
        __syncthreads();
        if (tid == 0) {
            float ts = 0.f, ts2 = 0.f;
            #pragma unroll
            for (int i = 0; i < 8; i++) { ts += rs[i]; ts2 += rs2[i]; }
            int slot = (rowTile >> 7) * 8 + (colTile >> 7);
            g_ps[slot] = ts; g_ps2[slot] = ts2;
        }
    }
}

__global__ __launch_bounds__(256, 2) void gemm_qkv_kernel(
    const float* __restrict__ Aq, const float* __restrict__ Akv,
    const float* __restrict__ wq, const float* __restrict__ wk, const float* __restrict__ wv,
    const float* __restrict__ bq, const float* __restrict__ bk, const float* __restrict__ bv)
{
    extern __shared__ float smem[];
    const float* A; const float* W; const float* bias; float* outp;
    int z = blockIdx.z;
    if (z == 0)      { A = Aq;  W = wq; bias = bq; outp = g_q; }
    else if (z == 1) { A = Akv; W = wk; bias = bk; outp = g_k; }
    else             { A = Akv; W = wv; bias = bv; outp = g_v; }
    gemm_core<0>(A, W, bias, outp, nullptr, 512, 512,
                 blockIdx.y * 128, blockIdx.x * 128, smem);
}

__global__ __launch_bounds__(256, 2) void gemm_ff1_kernel(
    const float* __restrict__ A, const float* __restrict__ W,
    const float* __restrict__ bias)
{
    extern __shared__ float smem[];
    gemm_core<1>(A, W, bias, g_h, nullptr, FFn, Cn,
                 blockIdx.y * 128, blockIdx.x * 128, smem);
}
__global__ __launch_bounds__(256, 2) void gemm_ff2_kernel(
    const float* __restrict__ W, const float* __restrict__ bias)
{
    extern __shared__ float smem[];
    gemm_core<2>(g_h, W, bias, g_y, g_y, Cn, FFn,
                 blockIdx.y * 128, blockIdx.x * 128, smem);
}

// ---------------- fused attention per (b,h) + residual-from-y add + LN stats ----------
#define QS 68
#define PS 132
#define ATTN_SMEM ((3*128*QS + 128*PS) * (int)sizeof(float))   // 172032 B

__global__ __launch_bounds__(256) void attn_kernel()
{
    extern __shared__ float sm[];
    float* Qs = sm;
    float* Ks = sm + 128*QS;
    float* Vs = sm + 2*128*QS;
    float* Ps = sm + 3*128*QS;

    int bh = blockIdx.x;
    int h = bh & (Hn - 1);
    int b = bh >> 3;
    int tid = threadIdx.x, wid = tid >> 5, lane = tid & 31;
    int g = lane >> 2, t = lane & 3;

    const float* qg = g_q + (size_t)b * Tn * Cn + h * DHn;
    const float* kg = g_k + (size_t)b * Sn * Cn + h * DHn;
    const float* vg = g_v + (size_t)b * Sn * Cn + h * DHn;

    for (int e = tid; e < Tn * DHn / 4; e += 256) {
        int r = e >> 4, d = (e & 15) * 4;
        size_t gi = (size_t)r * Cn + d;
        float4 q = *(const float4*)&qg[gi];
        float4 k = *(const float4*)&kg[gi];
        float4 v = *(const float4*)&vg[gi];
        float* qd = &Qs[r*QS + d];
        qd[0] = f2tff(q.x * 0.125f); qd[1] = f2tff(q.y * 0.125f);
        qd[2] = f2tff(q.z * 0.125f); qd[3] = f2tff(q.w * 0.125f);
        float* kd = &Ks[r*QS + d];
        kd[0] = f2tff(k.x); kd[1] = f2tff(k.y); kd[2] = f2tff(k.z); kd[3] = f2tff(k.w);
        float* vd = &Vs[r*QS + d];
        vd[0] = f2tff(v.x); vd[1] = f2tff(v.y); vd[2] = f2tff(v.z); vd[3] = f2tff(v.w);
    }
    __syncthreads();

    // ---- scores = (Q/8) @ K^T : 128x128. warps 2(M)x4(N) ----
    {
        int wm = wid >> 2, wn = wid & 3;
        float acc[4][4][4];
        #pragma unroll
        for (int i = 0; i < 4; i++)
            #pragma unroll
            for (int j = 0; j < 4; j++)
                #pragma unroll
                for (int q = 0; q < 4; q++) acc[i][j][q] = 0.f;

        const unsigned* Qu = (const unsigned*)Qs;
        const unsigned* Ku = (const unsigned*)Ks;
        #pragma unroll
        for (int ks = 0; ks < 8; ks++) {
            int c = ks*8 + t;
            unsigned a[4][4], bf[4][2];
            #pragma unroll
            for (int i = 0; i < 4; i++) {
                int r = wm*64 + i*16 + g;
                a[i][0] = Qu[r*QS + c];
                a[i][1] = Qu[(r+8)*QS + c];
                a[i][2] = Qu[r*QS + c + 4];
                a[i][3] = Qu[(r+8)*QS + c + 4];
            }
            #pragma unroll
            for (int j = 0; j < 4; j++) {
                int n = wn*32 + j*8 + g;
                bf[j][0] = Ku[n*QS + c];
                bf[j][1] = Ku[n*QS + c + 4];
            }
            #pragma unroll
            for (int i = 0; i < 4; i++)
                #pragma unroll
                for (int j = 0; j < 4; j++)
                    mma8(acc[i][j], a[i], bf[j]);
        }
        #pragma unroll
        for (int i = 0; i < 4; i++) {
            int r0 = wm*64 + i*16 + g;
            #pragma unroll
            for (int j = 0; j < 4; j++) {
                int c = wn*32 + j*8 + 2*t;
                *(float2*)&Ps[r0*PS + c]     = make_float2(acc[i][j][0], acc[i][j][1]);
                *(float2*)&Ps[(r0+8)*PS + c] = make_float2(acc[i][j][2], acc[i][j][3]);
            }
        }
    }
    __syncthreads();

    // ---- softmax: 2 threads per row ----
    {
        int row = tid >> 1;
        float* p = Ps + row*PS + (tid & 1) * 64;
        float mx = -1e30f;
        #pragma unroll 8
        for (int j = 0; j < 64; j++) mx = fmaxf(mx, p[j]);
        mx = fmaxf(mx, __shfl_xor_sync(0xffffffffu, mx, 1));
        float s = 0.f;
        #pragma unroll 8
        for (int j = 0; j < 64; j++) { float e = __expf(p[j] - mx); p[j] = e; s += e; }
        s += __shfl_xor_sync(0xffffffffu, s, 1);
        float inv = 1.f / s;
        #pragma unroll 8
        for (int j = 0; j < 64; j++) p[j] = f2tff(p[j] * inv);
    }
    __syncthreads();

    // ---- O = P @ V, fused residual (from y + prev stats) + stats. warps 4(M)x2(N) ----
    {
        int wm = wid >> 1, wn = wid & 1;
        float acc[2][4][4];
        #pragma unroll
        for (int i = 0; i < 2; i++)
            #pragma unroll
            for (int j = 0; j < 4; j++)
                #pragma unroll
                for (int q = 0; q < 4; q++) acc[i][j][q] = 0.f;

        const unsigned* Pu = (const unsigned*)Ps;
        const unsigned* Vu = (const unsigned*)Vs;
        #pragma unroll
        for (int ks = 0; ks < 16; ks++) {
            int c = ks*8 + t;
            unsigned a[2][4], bf[4][2];
            #pragma unroll
            for (int i = 0; i < 2; i++) {
                int r = wm*32 + i*16 + g;
                a[i][0] = Pu[r*PS + c];
                a[i][1] = Pu[(r+8)*PS + c];
                a[i][2] = Pu[r*PS + c + 4];
                a[i][3] = Pu[(r+8)*PS + c + 4];
            }
            #pragma unroll
            for (int j = 0; j < 4; j++) {
                int n = wn*32 + j*8 + g;
                bf[j][0] = Vu[c*QS + n];
                bf[j][1] = Vu[(c+4)*QS + n];
            }
            #pragma unroll
            for (int i = 0; i < 2; i++)
                #pragma unroll
                for (int j = 0; j < 4; j++)
                    mma8(acc[i][j], a[i], bf[j]);
        }

        float mu = g_mu[b], inv = g_inv[b];
        float* og = g_y + (size_t)b * Tn * Cn + (size_t)h * DHn;
        float s = 0.f, s2 = 0.f;
        #pragma unroll
        for (int i = 0; i < 2; i++) {
            int r0 = wm*32 + i*16 + g;
            #pragma unroll
            for (int j = 0; j < 4; j++) {
                int c = wn*32 + j*8 + 2*t;
                float2 x0 = *(const float2*)&og[(size_t)r0*Cn + c];
                float2 x1 = *(const float2*)&og[(size_t)(r0+8)*Cn + c];
                float v0 = acc[i][j][0] + (x0.x - mu) * inv;
                float v1 = acc[i][j][1] + (x0.y - mu) * inv;
                float v2 = acc[i][j][2] + (x1.x - mu) * inv;
                float v3 = acc[i][j][3] + (x1.y - mu) * inv;
                s  += v0 + v1 + v2 + v3;
                s2 += v0*v0 + v1*v1 + v2*v2 + v3*v3;
                *(float2*)&og[(size_t)r0*Cn + c]     = make_float2(v0, v1);
                *(float2*)&og[(size_t)(r0+8)*Cn + c] = make_float2(v2, v3);
            }
        }

        __shared__ float rs[8], rs2[8];
        #pragma unroll
        for (int o = 16; o > 0; o >>= 1) {
            s  += __shfl_xor_sync(0xffffffffu, s, o);
            s2 += __shfl_xor_sync(0xffffffffu, s2, o);
        }
        if (lane == 0) { rs[wid] = s; rs2[wid] = s2; }
        __syncthreads();
        if (tid == 0) {
            float ts = 0.f, ts2 = 0.f;
            #pragma unroll
            for (int i = 0; i < 8; i++) { ts += rs[i]; ts2 += rs2[i]; }
            g_ps[b*8 + h] = ts; g_ps2[b*8 + h] = ts2;
        }
    }
}

// --------- LN: slots -> (mu,inv); y -> xt (tf32), optional fp32 out -------------------
__global__ __launch_bounds__(256) void ln_norm_kernel(float* __restrict__ xout, int nslots)
{
    int b = blockIdx.y, chunk = blockIdx.x;
    float s = 0.f, s2 = 0.f;
    for (int i = 0; i < nslots; i++) { s += g_ps[b*8 + i]; s2 += g_ps2[b*8 + i]; }
    const float invN = 1.f / (Tn * Cn);
    float mu  = s * invN;
    float var = s2 * invN - mu * mu;
    float inv = rsqrtf(var + 1e-5f);
    if (chunk == 0 && threadIdx.x == 0) { g_mu[b] = mu; g_inv[b] = inv; }

    size_t base4 = ((size_t)b * Tn * Cn + (size_t)chunk * (Tn * Cn / 8)) / 4;
    const float4* y4 = (const float4*)g_y + base4;
    float4* xt4 = (float4*)g_xt + base4;
    const int n4 = Tn * Cn / 8 / 4;
    int tid = threadIdx.x;
    if (xout) {
        float4* x4 = (float4*)xout + base4;
        for (int i = tid; i < n4; i += 256) {
            float4 a = y4[i];
            a.x = (a.x - mu) * inv; a.y = (a.y - mu) * inv;
            a.z = (a.z - mu) * inv; a.w = (a.w - mu) * inv;
            x4[i] = a;
            float4 tv;
            tv.x = f2tff(a.x); tv.y = f2tff(a.y); tv.z = f2tff(a.z); tv.w = f2tff(a.w);
            xt4[i] = tv;
        }
    } else {
        for (int i = tid; i < n4; i += 256) {
            float4 a = y4[i];
            float4 tv;
            tv.x = f2tff((a.x - mu) * inv); tv.y = f2tff((a.y - mu) * inv);
            tv.z = f2tff((a.z - mu) * inv); tv.w = f2tff((a.w - mu) * inv);
            xt4[i] = tv;
        }
    }
}

// ---------------- driver ----------------
extern "C" void kernel_launch(void* const* d_in, const int* in_sizes, int n_in,
                              void* d_out, int out_size)
{
    const float* x     = (const float*)d_in[0];
    const float* enc   = (const float*)d_in[1];
    const float* sa_wq = (const float*)d_in[2];  const float* sa_bq = (const float*)d_in[3];
    const float* sa_wk = (const float*)d_in[4];  const float* sa_bk = (const float*)d_in[5];
    const float* sa_wv = (const float*)d_in[6];  const float* sa_bv = (const float*)d_in[7];
    const float* ca_wq = (const float*)d_in[8];  const float* ca_bq = (const float*)d_in[9];
    const float* ca_wk = (const float*)d_in[10]; const float* ca_bk = (const float*)d_in[11];
    const float* ca_wv = (const float*)d_in[12]; const float* ca_bv = (const float*)d_in[13];
    const float* ff_w1 = (const float*)d_in[14]; const float* ff_b1 = (const float*)d_in[15];
    const float* ff_w2 = (const float*)d_in[16]; const float* ff_b2 = (const float*)d_in[17];
    float* out = (float*)d_out;

    cudaFuncSetAttribute(attn_kernel, cudaFuncAttributeMaxDynamicSharedMemorySize, ATTN_SMEM);
    cudaFuncSetAttribute(gemm_qkv_kernel, cudaFuncAttributeMaxDynamicSharedMemorySize, GEMM_SMEM);
    cudaFuncSetAttribute(gemm_ff1_kernel, cudaFuncAttributeMaxDynamicSharedMemorySize, GEMM_SMEM);
    cudaFuncSetAttribute(gemm_ff2_kernel, cudaFuncAttributeMaxDynamicSharedMemorySize, GEMM_SMEM);

    float *wsaq, *wsak, *wsav, *wcaq, *wcak, *wcav, *wff1, *wff2, *xt, *enct, *yb;
    cudaGetSymbolAddress((void**)&wsaq, g_wsaq);
    cudaGetSymbolAddress((void**)&wsak, g_wsak);
    cudaGetSymbolAddress((void**)&wsav, g_wsav);
    cudaGetSymbolAddress((void**)&wcaq, g_wcaq);
    cudaGetSymbolAddress((void**)&wcak, g_wcak);
    cudaGetSymbolAddress((void**)&wcav, g_wcav);
    cudaGetSymbolAddress((void**)&wff1, g_wff1);
    cudaGetSymbolAddress((void**)&wff2, g_wff2);
    cudaGetSymbolAddress((void**)&xt,   g_xt);
    cudaGetSymbolAddress((void**)&enct, g_enct);
    cudaGetSymbolAddress((void**)&yb,   g_y);

    const int nAct = Bn * Tn * Cn;
    cudaMemcpyAsync(yb, x, sizeof(float) * nAct, cudaMemcpyDeviceToDevice);
    init_stats_kernel<<<1, 64>>>();
    cvt_kernel<<<(nAct + 255) / 256, 256>>>(x, xt, nAct);
    cvt_kernel<<<(nAct + 255) / 256, 256>>>(enc, enct, nAct);
    const int nQW = Ln * Hn * Cn * DHn;
    cvt_qkvw_kernel<<<nQW / 256, 256>>>(sa_wq, wsaq);
    cvt_qkvw_kernel<<<nQW / 256, 256>>>(sa_wk, wsak);
    cvt_qkvw_kernel<<<nQW / 256, 256>>>(sa_wv, wsav);
    cvt_qkvw_kernel<<<nQW / 256, 256>>>(ca_wq, wcaq);
    cvt_qkvw_kernel<<<nQW / 256, 256>>>(ca_wk, wcak);
    cvt_qkvw_kernel<<<nQW / 256, 256>>>(ca_wv, wcav);
    const int nFW = Ln * Cn * FFn;
    cvt_kernel<<<(nFW + 255) / 256, 256>>>(ff_w1, wff1, nFW);
    cvt_kernel<<<(nFW + 255) / 256, 256>>>(ff_w2, wff2, nFW);

    const size_t WSTRIDE = (size_t)Cn * 512;
    const size_t BSTRIDE = (size_t)Hn * DHn;

    for (int l = 0; l < Ln; l++) {
        // ---- self attention ----
        gemm_qkv_kernel<<<dim3(4, 64, 3), 256, GEMM_SMEM>>>(xt, xt,
            wsaq + l * WSTRIDE, wsak + l * WSTRIDE, wsav + l * WSTRIDE,
            sa_bq + l * BSTRIDE, sa_bk + l * BSTRIDE, sa_bv + l * BSTRIDE);
        attn_kernel<<<Bn * Hn, 256, ATTN_SMEM>>>();
        ln_norm_kernel<<<dim3(8, Bn), 256>>>(nullptr, 8);

        // ---- cross attention ----
        gemm_qkv_kernel<<<dim3(4, 64, 3), 256, GEMM_SMEM>>>(xt, enct,
            wcaq + l * WSTRIDE, wcak + l * WSTRIDE, wcav + l * WSTRIDE,
            ca_bq + l * BSTRIDE, ca_bk + l * BSTRIDE, ca_bv + l * BSTRIDE);
        attn_kernel<<<Bn * Hn, 256, ATTN_SMEM>>>();
        ln_norm_kernel<<<dim3(8, Bn), 256>>>(nullptr, 8);

        // ---- feed forward ----
        gemm_ff1_kernel<<<dim3(FFn / 128, (Bn * Tn) / 128), 256, GEMM_SMEM>>>(
            xt, wff1 + (size_t)l * Cn * FFn, ff_b1 + (size_t)l * FFn);
        gemm_ff2_kernel<<<dim3(Cn / 128, (Bn * Tn) / 128), 256, GEMM_SMEM>>>(
            wff2 + (size_t)l * FFn * Cn, ff_b2 + (size_t)l * Cn);
        // FF2 col tiles = Cn/128 = 4 -> 4 stat slots per batch
        ln_norm_kernel<<<dim3(8, Bn), 256>>>((l == Ln - 1) ? out : nullptr, 4);
    }
}

// round 16
// speedup vs baseline: 1.4809x; 1.3448x over previous
#include <cuda_runtime.h>
#include <cuda_fp16.h>

#define Bn 64
#define Tn 128
#define Sn 128
#define Cn 512
#define Hn 8
#define DHn 64
#define FFn 2048
#define Ln 6

// ---------------- scratch (device globals; no allocation allowed) ----------------
__device__ float g_q[Bn*Tn*Cn];           // [B*T, H*DH] fp32 (attention input)
__device__ float g_k[Bn*Sn*Cn];
__device__ float g_v[Bn*Sn*Cn];
__device__ float g_y[Bn*Tn*Cn];           // pre-norm y = x + residual (fp32)
__device__ __half g_h[(size_t)Bn*Tn*FFn]; // FF hidden (fp16)
__device__ __half g_xt[Bn*Tn*Cn];         // fp16 mirror of normalized x
__device__ __half g_enct[Bn*Sn*Cn];       // fp16 mirror of encoder output
__device__ float g_ps[Bn*8], g_ps2[Bn*8]; // LN partial stats (slots)
__device__ float g_mu[Bn], g_inv[Bn];     // committed LN stats of previous stage
// fp16 weights, transposed to [N][K] (n-major, k contiguous)
__device__ __half g_wsaq[Ln*Cn*Cn], g_wsak[Ln*Cn*Cn], g_wsav[Ln*Cn*Cn];
__device__ __half g_wcaq[Ln*Cn*Cn], g_wcak[Ln*Cn*Cn], g_wcav[Ln*Cn*Cn];
__device__ __half g_wff1[(size_t)Ln*Cn*FFn];   // [L][FF][C]
__device__ __half g_wff2[(size_t)Ln*FFn*Cn];   // [L][C][FF]

// ---------------- helpers ----------------
__device__ __forceinline__ unsigned f2tf(float f) {
    unsigned u;
    asm("cvt.rna.tf32.f32 %0, %1;" : "=r"(u) : "f"(f));
    return u;
}
__device__ __forceinline__ float f2tff(float f) { return __uint_as_float(f2tf(f)); }
// tf32 mma (attention path)
__device__ __forceinline__ void mma8(float c[4], const unsigned a[4], const unsigned b[2]) {
    asm volatile("mma.sync.aligned.m16n8k8.row.col.f32.tf32.tf32.f32 "
        "{%0,%1,%2,%3}, {%4,%5,%6,%7}, {%8,%9}, {%0,%1,%2,%3};"
        : "+f"(c[0]), "+f"(c[1]), "+f"(c[2]), "+f"(c[3])
        : "r"(a[0]), "r"(a[1]), "r"(a[2]), "r"(a[3]), "r"(b[0]), "r"(b[1]));
}
// fp16 mma (GEMM path), fp32 accumulate
__device__ __forceinline__ void mma16(float c[4], const unsigned a[4], const unsigned b[2]) {
    asm volatile("mma.sync.aligned.m16n8k16.row.col.f32.f16.f16.f32 "
        "{%0,%1,%2,%3}, {%4,%5,%6,%7}, {%8,%9}, {%0,%1,%2,%3};"
        : "+f"(c[0]), "+f"(c[1]), "+f"(c[2]), "+f"(c[3])
        : "r"(a[0]), "r"(a[1]), "r"(a[2]), "r"(a[3]), "r"(b[0]), "r"(b[1]));
}
__device__ __forceinline__ void cpasync16(void* s, const void* g) {
    unsigned sa = (unsigned)__cvta_generic_to_shared(s);
    asm volatile("cp.async.cg.shared.global [%0], [%1], 16;" :: "r"(sa), "l"(g));
}

// ---------------- one-time conversion kernels ----------------
__global__ void cvt_h_kernel(const float* __restrict__ src, __half* __restrict__ dst, int n) {
    int i = blockIdx.x * 256 + threadIdx.x;
    if (i < n) dst[i] = __float2half_rn(src[i]);
}
// tiled transpose-convert: [R][C] fp32 -> [C][R] fp16, batched
__global__ void tcvt_kernel(const float* __restrict__ src, __half* __restrict__ dst,
                            int R, int C, size_t sstride, size_t dstride)
{
    __shared__ float tile[32][33];
    const float* s = src + blockIdx.z * sstride;
    __half* d = dst + blockIdx.z * dstride;
    int r0 = blockIdx.y * 32, c0 = blockIdx.x * 32;
    int tx = threadIdx.x;
    #pragma unroll
    for (int i = threadIdx.y; i < 32; i += 8)
        tile[i][tx] = s[(size_t)(r0 + i) * C + c0 + tx];
    __syncthreads();
    #pragma unroll
    for (int i = threadIdx.y; i < 32; i += 8)
        d[(size_t)(c0 + i) * R + r0 + tx] = __float2half_rn(tile[tx][i]);
}
__global__ void init_stats_kernel() {
    int i = threadIdx.x;
    if (i < Bn) { g_mu[i] = 0.f; g_inv[i] = 1.f; }
}

// ------ fp16 GEMM: block 128x128, warp 64x32, m16n8k16, 3-stage cp.async --------------
// A [M][K] fp16 row-major; W [N][K] fp16 (pre-transposed, k contiguous = col-major B).
// smem rows stride 40 halves (80 B): bank = (row*20 + t) mod 32, all 32 distinct ->
// every half2 fragment LDS is conflict-free for both A and B.
#define RSH 40                        // halves per smem row (32 data + 8 pad)
#define TBUF (128*RSH)                // halves per operand per stage
#define NSTG 3
#define GEMM_SMEM (NSTG * 2 * TBUF * (int)sizeof(__half))   // 61440 B

// EPI: 0 = bias only (fp32 out), 1 = relu -> fp16 out, 2 = residual-from-y + LN stats
template<int EPI>
__device__ __forceinline__ void gemm_core(
    const __half* __restrict__ A, const __half* __restrict__ W,
    const float* __restrict__ bias, void* __restrict__ outp,
    int N, int K, int rowTile, int colTile, __half* smem)
{
    __half* As = smem;
    __half* Bs = smem + NSTG * TBUF;

    int tid = threadIdx.x, wid = tid >> 5, lane = tid & 31;
    int wm = wid >> 2, wn = wid & 3;        // 2(M) x 4(N) warps, warp 64x32
    int g = lane >> 2, t = lane & 3;

    float acc[4][4][4];
    #pragma unroll
    for (int i = 0; i < 4; i++)
        #pragma unroll
        for (int j = 0; j < 4; j++)
            #pragma unroll
            for (int q = 0; q < 4; q++) acc[i][j][q] = 0.f;

    const __half* Ab = A + (size_t)rowTile * K;
    const __half* Wb = W + (size_t)colTile * K;
    int KT = K >> 5;                        // 32-k slabs

    // prologue: stage slabs 0, 1 (A row: 64B = 4 x 16B chunks; 512 chunks each op)
    #pragma unroll
    for (int st = 0; st < 2; st++) {
        int k0 = st << 5;
        __half* Ad = As + st * TBUF;
        __half* Bd = Bs + st * TBUF;
        #pragma unroll
        for (int j = 0; j < 2; j++) {
            int q = tid + j * 256; int r = q >> 2, ko = (q & 3) * 8;
            cpasync16(&Ad[r * RSH + ko], &Ab[(size_t)r * K + k0 + ko]);
        }
        #pragma unroll
        for (int j = 0; j < 2; j++) {
            int q = tid + j * 256; int r = q >> 2, ko = (q & 3) * 8;
            cpasync16(&Bd[r * RSH + ko], &Wb[(size_t)r * K + k0 + ko]);
        }
        asm volatile("cp.async.commit_group;");
    }

    int buf = 0;
    for (int kt = 0; kt < KT; kt++) {
        asm volatile("cp.async.wait_group 1;");
        __syncthreads();

        const unsigned* Au = (const unsigned*)(As + buf * TBUF);   // 20 unsigned/row
        const unsigned* Bu = (const unsigned*)(Bs + buf * TBUF);
        #pragma unroll
        for (int ks = 0; ks < 2; ks++) {            // two k16 groups per slab
            int c = ks * 8 + t;                     // half2 col index (k = 2t, 2t+1)
            unsigned a[4][4], bfr[4][2];
            #pragma unroll
            for (int i = 0; i < 4; i++) {
                int r = wm * 64 + i * 16 + g;
                a[i][0] = Au[r * 20 + c];           // rows g,   k 2t..2t+1
                a[i][1] = Au[(r + 8) * 20 + c];     // rows g+8
                a[i][2] = Au[r * 20 + c + 4];       // k 2t+8..2t+9
                a[i][3] = Au[(r + 8) * 20 + c + 4];
            }
            #pragma unroll
            for (int j = 0; j < 4; j++) {
                int n = wn * 32 + j * 8 + g;
                bfr[j][0] = Bu[n * 20 + c];         // B[k=2t..2t+1][n]
                bfr[j][1] = Bu[n * 20 + c + 4];     // B[k=2t+8..2t+9][n]
            }
            #pragma unroll
            for (int i = 0; i < 4; i++)
                #pragma unroll
                for (int j = 0; j < 4; j++)
                    mma16(acc[i][j], a[i], bfr[j]);
        }

        // prefetch slab kt+2 into the free buffer
        if (kt + 2 < KT) {
            int k0 = (kt + 2) << 5;
            int nb = kt + 2; nb -= (nb / NSTG) * NSTG;
            __half* Ad = As + nb * TBUF;
            __half* Bd = Bs + nb * TBUF;
            #pragma unroll
            for (int j = 0; j < 2; j++) {
                int q = tid + j * 256; int r = q >> 2, ko = (q & 3) * 8;
                cpasync16(&Ad[r * RSH + ko], &Ab[(size_t)r * K + k0 + ko]);
            }
            #pragma unroll
            for (int j = 0; j < 2; j++) {
                int q = tid + j * 256; int r = q >> 2, ko = (q & 3) * 8;
                cpasync16(&Bd[r * RSH + ko], &Wb[(size_t)r * K + k0 + ko]);
            }
        }
        asm volatile("cp.async.commit_group;");

        buf++; if (buf == NSTG) buf = 0;
    }

    float s = 0.f, s2 = 0.f;
    float mu = 0.f, inv = 1.f;
    if (EPI == 2) { mu = g_mu[rowTile >> 7]; inv = g_inv[rowTile >> 7]; }
    #pragma unroll
    for (int i = 0; i < 4; i++) {
        int r0 = rowTile + wm * 64 + i * 16 + g;
        #pragma unroll
        for (int j = 0; j < 4; j++) {
            int c = colTile + wn * 32 + j * 8 + 2 * t;
            float b0 = bias[c], b1 = bias[c + 1];
            float v0 = acc[i][j][0] + b0, v1 = acc[i][j][1] + b1;
            float v2 = acc[i][j][2] + b0, v3 = acc[i][j][3] + b1;
            if (EPI == 1) {
                // relu + fp16 round, out = g_h
                __half2* oh = (__half2*)outp;
                oh[((size_t)r0 * N + c) >> 1]       = __floats2half2_rn(fmaxf(v0, 0.f), fmaxf(v1, 0.f));
                oh[((size_t)(r0 + 8) * N + c) >> 1] = __floats2half2_rn(fmaxf(v2, 0.f), fmaxf(v3, 0.f));
            } else {
                float* of = (float*)outp;
                if (EPI == 2) {
                    const float* resid = (const float*)outp;  // g_y in-place
                    float2 x0 = *(const float2*)&resid[(size_t)r0 * N + c];
                    float2 x1 = *(const float2*)&resid[(size_t)(r0 + 8) * N + c];
                    v0 += (x0.x - mu) * inv; v1 += (x0.y - mu) * inv;
                    v2 += (x1.x - mu) * inv; v3 += (x1.y - mu) * inv;
                    s  += v0 + v1 + v2 + v3;
                    s2 += v0*v0 + v1*v1 + v2*v2 + v3*v3;
                }
                *(float2*)&of[(size_t)r0 * N + c]       = make_float2(v0, v1);
                *(float2*)&of[(size_t)(r0 + 8) * N + c] = make_float2(v2, v3);
            }
        }
    }

    if (EPI == 2) {
        __shared__ float rs[8], rs2[8];
        #pragma unroll
        for (int o = 16; o > 0; o >>= 1) {
            s  += __shfl_xor_sync(0xffffffffu, s, o);
            s2 += __shfl_xor_sync(0xffffffffu, s2, o);
        }
        if (lane == 0) { rs[wid] = s; rs2[wid] = s2; }
        __syncthreads();
        if (tid == 0) {
            float ts = 0.f, ts2 = 0.f;
            #pragma unroll
            for (int i = 0; i < 8; i++) { ts += rs[i]; ts2 += rs2[i]; }
            int slot = (rowTile >> 7) * 8 + (colTile >> 7);
            g_ps[slot] = ts; g_ps2[slot] = ts2;
        }
    }
}

__global__ __launch_bounds__(256, 2) void gemm_qkv_kernel(
    const __half* __restrict__ Aq, const __half* __restrict__ Akv,
    const __half* __restrict__ wq, const __half* __restrict__ wk, const __half* __restrict__ wv,
    const float* __restrict__ bq, const float* __restrict__ bk, const float* __restrict__ bv)
{
    extern __shared__ __half hsmem[];
    const __half* A; const __half* W; const float* bias; float* outp;
    int z = blockIdx.z;
    if (z == 0)      { A = Aq;  W = wq; bias = bq; outp = g_q; }
    else if (z == 1) { A = Akv; W = wk; bias = bk; outp = g_k; }
    else             { A = Akv; W = wv; bias = bv; outp = g_v; }
    gemm_core<0>(A, W, bias, outp, 512, 512,
                 blockIdx.y * 128, blockIdx.x * 128, hsmem);
}

__global__ __launch_bounds__(256, 2) void gemm_ff1_kernel(
    const __half* __restrict__ A, const __half* __restrict__ W,
    const float* __restrict__ bias)
{
    extern __shared__ __half hsmem[];
    gemm_core<1>(A, W, bias, g_h, FFn, Cn,
                 blockIdx.y * 128, blockIdx.x * 128, hsmem);
}
__global__ __launch_bounds__(256, 2) void gemm_ff2_kernel(
    const __half* __restrict__ W, const float* __restrict__ bias)
{
    extern __shared__ __half hsmem[];
    gemm_core<2>(g_h, W, bias, g_y, Cn, FFn,
                 blockIdx.y * 128, blockIdx.x * 128, hsmem);
}

// ---------------- fused attention per (b,h) + residual-from-y add + LN stats ----------
// (unchanged tf32 path, ~8% of runtime)
#define QS 68
#define PS 132
#define ATTN_SMEM ((3*128*QS + 128*PS) * (int)sizeof(float))   // 172032 B

__global__ __launch_bounds__(256) void attn_kernel()
{
    extern __shared__ float sm[];
    float* Qs = sm;
    float* Ks = sm + 128*QS;
    float* Vs = sm + 2*128*QS;
    float* Ps = sm + 3*128*QS;

    int bh = blockIdx.x;
    int h = bh & (Hn - 1);
    int b = bh >> 3;
    int tid = threadIdx.x, wid = tid >> 5, lane = tid & 31;
    int g = lane >> 2, t = lane & 3;

    const float* qg = g_q + (size_t)b * Tn * Cn + h * DHn;
    const float* kg = g_k + (size_t)b * Sn * Cn + h * DHn;
    const float* vg = g_v + (size_t)b * Sn * Cn + h * DHn;

    for (int e = tid; e < Tn * DHn / 4; e += 256) {
        int r = e >> 4, d = (e & 15) * 4;
        size_t gi = (size_t)r * Cn + d;
        float4 q = *(const float4*)&qg[gi];
        float4 k = *(const float4*)&kg[gi];
        float4 v = *(const float4*)&vg[gi];
        float* qd = &Qs[r*QS + d];
        qd[0] = f2tff(q.x * 0.125f); qd[1] = f2tff(q.y * 0.125f);
        qd[2] = f2tff(q.z * 0.125f); qd[3] = f2tff(q.w * 0.125f);
        float* kd = &Ks[r*QS + d];
        kd[0] = f2tff(k.x); kd[1] = f2tff(k.y); kd[2] = f2tff(k.z); kd[3] = f2tff(k.w);
        float* vd = &Vs[r*QS + d];
        vd[0] = f2tff(v.x); vd[1] = f2tff(v.y); vd[2] = f2tff(v.z); vd[3] = f2tff(v.w);
    }
    __syncthreads();

    // ---- scores = (Q/8) @ K^T : 128x128. warps 2(M)x4(N) ----
    {
        int wm = wid >> 2, wn = wid & 3;
        float acc[4][4][4];
        #pragma unroll
        for (int i = 0; i < 4; i++)
            #pragma unroll
            for (int j = 0; j < 4; j++)
                #pragma unroll
                for (int q = 0; q < 4; q++) acc[i][j][q] = 0.f;

        const unsigned* Qu = (const unsigned*)Qs;
        const unsigned* Ku = (const unsigned*)Ks;
        #pragma unroll
        for (int ks = 0; ks < 8; ks++) {
            int c = ks*8 + t;
            unsigned a[4][4], bf[4][2];
            #pragma unroll
            for (int i = 0; i < 4; i++) {
                int r = wm*64 + i*16 + g;
                a[i][0] = Qu[r*QS + c];
                a[i][1] = Qu[(r+8)*QS + c];
                a[i][2] = Qu[r*QS + c + 4];
                a[i][3] = Qu[(r+8)*QS + c + 4];
            }
            #pragma unroll
            for (int j = 0; j < 4; j++) {
                int n = wn*32 + j*8 + g;
                bf[j][0] = Ku[n*QS + c];
                bf[j][1] = Ku[n*QS + c + 4];
            }
            #pragma unroll
            for (int i = 0; i < 4; i++)
                #pragma unroll
                for (int j = 0; j < 4; j++)
                    mma8(acc[i][j], a[i], bf[j]);
        }
        #pragma unroll
        for (int i = 0; i < 4; i++) {
            int r0 = wm*64 + i*16 + g;
            #pragma unroll
            for (int j = 0; j < 4; j++) {
                int c = wn*32 + j*8 + 2*t;
                *(float2*)&Ps[r0*PS + c]     = make_float2(acc[i][j][0], acc[i][j][1]);
                *(float2*)&Ps[(r0+8)*PS + c] = make_float2(acc[i][j][2], acc[i][j][3]);
            }
        }
    }
    __syncthreads();

    // ---- softmax: 2 threads per row ----
    {
        int row = tid >> 1;
        float* p = Ps + row*PS + (tid & 1) * 64;
        float mx = -1e30f;
        #pragma unroll 8
        for (int j = 0; j < 64; j++) mx = fmaxf(mx, p[j]);
        mx = fmaxf(mx, __shfl_xor_sync(0xffffffffu, mx, 1));
        float s = 0.f;
        #pragma unroll 8
        for (int j = 0; j < 64; j++) { float e = __expf(p[j] - mx); p[j] = e; s += e; }
        s += __shfl_xor_sync(0xffffffffu, s, 1);
        float inv = 1.f / s;
        #pragma unroll 8
        for (int j = 0; j < 64; j++) p[j] = f2tff(p[j] * inv);
    }
    __syncthreads();

    // ---- O = P @ V, fused residual (from y + prev stats) + stats. warps 4(M)x2(N) ----
    {
        int wm = wid >> 1, wn = wid & 1;
        float acc[2][4][4];
        #pragma unroll
        for (int i = 0; i < 2; i++)
            #pragma unroll
            for (int j = 0; j < 4; j++)
                #pragma unroll
                for (int q = 0; q < 4; q++) acc[i][j][q] = 0.f;

        const unsigned* Pu = (const unsigned*)Ps;
        const unsigned* Vu = (const unsigned*)Vs;
        #pragma unroll
        for (int ks = 0; ks < 16; ks++) {
            int c = ks*8 + t;
            unsigned a[2][4], bf[4][2];
            #pragma unroll
            for (int i = 0; i < 2; i++) {
                int r = wm*32 + i*16 + g;
                a[i][0] = Pu[r*PS + c];
                a[i][1] = Pu[(r+8)*PS + c];
                a[i][2] = Pu[r*PS + c + 4];
                a[i][3] = Pu[(r+8)*PS + c + 4];
            }
            #pragma unroll
            for (int j = 0; j < 4; j++) {
                int n = wn*32 + j*8 + g;
                bf[j][0] = Vu[c*QS + n];
                bf[j][1] = Vu[(c+4)*QS + n];
            }
            #pragma unroll
            for (int i = 0; i < 2; i++)
                #pragma unroll
                for (int j = 0; j < 4; j++)
                    mma8(acc[i][j], a[i], bf[j]);
        }

        float mu = g_mu[b], inv = g_inv[b];
        float* og = g_y + (size_t)b * Tn * Cn + (size_t)h * DHn;
        float s = 0.f, s2 = 0.f;
        #pragma unroll
        for (int i = 0; i < 2; i++) {
            int r0 = wm*32 + i*16 + g;
            #pragma unroll
            for (int j = 0; j < 4; j++) {
                int c = wn*32 + j*8 + 2*t;
                float2 x0 = *(const float2*)&og[(size_t)r0*Cn + c];
                float2 x1 = *(const float2*)&og[(size_t)(r0+8)*Cn + c];
                float v0 = acc[i][j][0] + (x0.x - mu) * inv;
                float v1 = acc[i][j][1] + (x0.y - mu) * inv;
                float v2 = acc[i][j][2] + (x1.x - mu) * inv;
                float v3 = acc[i][j][3] + (x1.y - mu) * inv;
                s  += v0 + v1 + v2 + v3;
                s2 += v0*v0 + v1*v1 + v2*v2 + v3*v3;
                *(float2*)&og[(size_t)r0*Cn + c]     = make_float2(v0, v1);
                *(float2*)&og[(size_t)(r0+8)*Cn + c] = make_float2(v2, v3);
            }
        }

        __shared__ float rs[8], rs2[8];
        #pragma unroll
        for (int o = 16; o > 0; o >>= 1) {
            s  += __shfl_xor_sync(0xffffffffu, s, o);
            s2 += __shfl_xor_sync(0xffffffffu, s2, o);
        }
        if (lane == 0) { rs[wid] = s; rs2[wid] = s2; }
        __syncthreads();
        if (tid == 0) {
            float ts = 0.f, ts2 = 0.f;
            #pragma unroll
            for (int i = 0; i < 8; i++) { ts += rs[i]; ts2 += rs2[i]; }
            g_ps[b*8 + h] = ts; g_ps2[b*8 + h] = ts2;
        }
    }
}

// --------- LN: slots -> (mu,inv); y -> xt (fp16), optional fp32 out -------------------
__global__ __launch_bounds__(256) void ln_norm_kernel(float* __restrict__ xout, int nslots)
{
    int b = blockIdx.y, chunk = blockIdx.x;
    float s = 0.f, s2 = 0.f;
    for (int i = 0; i < nslots; i++) { s += g_ps[b*8 + i]; s2 += g_ps2[b*8 + i]; }
    const float invN = 1.f / (Tn * Cn);
    float mu  = s * invN;
    float var = s2 * invN - mu * mu;
    float inv = rsqrtf(var + 1e-5f);
    if (chunk == 0 && threadIdx.x == 0) { g_mu[b] = mu; g_inv[b] = inv; }

    size_t base4 = ((size_t)b * Tn * Cn + (size_t)chunk * (Tn * Cn / 8)) / 4;
    const float4* y4 = (const float4*)g_y + base4;
    __half2* xt2 = (__half2*)g_xt + base4 * 2;
    const int n4 = Tn * Cn / 8 / 4;
    int tid = threadIdx.x;
    if (xout) {
        float4* x4 = (float4*)xout + base4;
        for (int i = tid; i < n4; i += 256) {
            float4 a = y4[i];
            a.x = (a.x - mu) * inv; a.y = (a.y - mu) * inv;
            a.z = (a.z - mu) * inv; a.w = (a.w - mu) * inv;
            x4[i] = a;
            xt2[2*i]   = __floats2half2_rn(a.x, a.y);
            xt2[2*i+1] = __floats2half2_rn(a.z, a.w);
        }
    } else {
        for (int i = tid; i < n4; i += 256) {
            float4 a = y4[i];
            xt2[2*i]   = __floats2half2_rn((a.x - mu) * inv, (a.y - mu) * inv);
            xt2[2*i+1] = __floats2half2_rn((a.z - mu) * inv, (a.w - mu) * inv);
        }
    }
}

// ---------------- driver ----------------
extern "C" void kernel_launch(void* const* d_in, const int* in_sizes, int n_in,
                              void* d_out, int out_size)
{
    const float* x     = (const float*)d_in[0];
    const float* enc   = (const float*)d_in[1];
    const float* sa_wq = (const float*)d_in[2];  const float* sa_bq = (const float*)d_in[3];
    const float* sa_wk = (const float*)d_in[4];  const float* sa_bk = (const float*)d_in[5];
    const float* sa_wv = (const float*)d_in[6];  const float* sa_bv = (const float*)d_in[7];
    const float* ca_wq = (const float*)d_in[8];  const float* ca_bq = (const float*)d_in[9];
    const float* ca_wk = (const float*)d_in[10]; const float* ca_bk = (const float*)d_in[11];
    const float* ca_wv = (const float*)d_in[12]; const float* ca_bv = (const float*)d_in[13];
    const float* ff_w1 = (const float*)d_in[14]; const float* ff_b1 = (const float*)d_in[15];
    const float* ff_w2 = (const float*)d_in[16]; const float* ff_b2 = (const float*)d_in[17];
    float* out = (float*)d_out;

    cudaFuncSetAttribute(attn_kernel, cudaFuncAttributeMaxDynamicSharedMemorySize, ATTN_SMEM);
    cudaFuncSetAttribute(gemm_qkv_kernel, cudaFuncAttributeMaxDynamicSharedMemorySize, GEMM_SMEM);
    cudaFuncSetAttribute(gemm_ff1_kernel, cudaFuncAttributeMaxDynamicSharedMemorySize, GEMM_SMEM);
    cudaFuncSetAttribute(gemm_ff2_kernel, cudaFuncAttributeMaxDynamicSharedMemorySize, GEMM_SMEM);

    __half *wsaq, *wsak, *wsav, *wcaq, *wcak, *wcav, *wff1, *wff2, *xt, *enct;
    float *yb;
    cudaGetSymbolAddress((void**)&wsaq, g_wsaq);
    cudaGetSymbolAddress((void**)&wsak, g_wsak);
    cudaGetSymbolAddress((void**)&wsav, g_wsav);
    cudaGetSymbolAddress((void**)&wcaq, g_wcaq);
    cudaGetSymbolAddress((void**)&wcak, g_wcak);
    cudaGetSymbolAddress((void**)&wcav, g_wcav);
    cudaGetSymbolAddress((void**)&wff1, g_wff1);
    cudaGetSymbolAddress((void**)&wff2, g_wff2);
    cudaGetSymbolAddress((void**)&xt,   g_xt);
    cudaGetSymbolAddress((void**)&enct, g_enct);
    cudaGetSymbolAddress((void**)&yb,   g_y);

    const int nAct = Bn * Tn * Cn;
    cudaMemcpyAsync(yb, x, sizeof(float) * nAct, cudaMemcpyDeviceToDevice);
    init_stats_kernel<<<1, 64>>>();
    cvt_h_kernel<<<(nAct + 255) / 256, 256>>>(x, xt, nAct);
    cvt_h_kernel<<<(nAct + 255) / 256, 256>>>(enc, enct, nAct);

    // qkv weights: per (l,h) transpose [C=512][DH=64] -> [64][512]; dst batch stride 64*512
    dim3 tb(32, 8);
    tcvt_kernel<<<dim3(DHn/32, Cn/32, Ln*Hn), tb>>>(sa_wq, wsaq, Cn, DHn, (size_t)Cn*DHn, (size_t)DHn*Cn);
    tcvt_kernel<<<dim3(DHn/32, Cn/32, Ln*Hn), tb>>>(sa_wk, wsak, Cn, DHn, (size_t)Cn*DHn, (size_t)DHn*Cn);
    tcvt_kernel<<<dim3(DHn/32, Cn/32, Ln*Hn), tb>>>(sa_wv, wsav, Cn, DHn, (size_t)Cn*DHn, (size_t)DHn*Cn);
    tcvt_kernel<<<dim3(DHn/32, Cn/32, Ln*Hn), tb>>>(ca_wq, wcaq, Cn, DHn, (size_t)Cn*DHn, (size_t)DHn*Cn);
    tcvt_kernel<<<dim3(DHn/32, Cn/32, Ln*Hn), tb>>>(ca_wk, wcak, Cn, DHn, (size_t)Cn*DHn, (size_t)DHn*Cn);
    tcvt_kernel<<<dim3(DHn/32, Cn/32, Ln*Hn), tb>>>(ca_wv, wcav, Cn, DHn, (size_t)Cn*DHn, (size_t)DHn*Cn);
    // ff1: [C=512][FF=2048] -> [FF][C]
    tcvt_kernel<<<dim3(FFn/32, Cn/32, Ln), tb>>>(ff_w1, wff1, Cn, FFn, (size_t)Cn*FFn, (size_t)Cn*FFn);
    // ff2: [FF=2048][C=512] -> [C][FF]
    tcvt_kernel<<<dim3(Cn/32, FFn/32, Ln), tb>>>(ff_w2, wff2, FFn, Cn, (size_t)FFn*Cn, (size_t)FFn*Cn);

    const size_t WSTRIDE = (size_t)Cn * 512;   // per-layer qkv weight stride ([512][512])
    const size_t BSTRIDE = (size_t)Hn * DHn;

    for (int l = 0; l < Ln; l++) {
        // ---- self attention ----
        gemm_qkv_kernel<<<dim3(4, 64, 3), 256, GEMM_SMEM>>>(xt, xt,
            wsaq + l * WSTRIDE, wsak + l * WSTRIDE, wsav + l * WSTRIDE,
            sa_bq + l * BSTRIDE, sa_bk + l * BSTRIDE, sa_bv + l * BSTRIDE);
        attn_kernel<<<Bn * Hn, 256, ATTN_SMEM>>>();
        ln_norm_kernel<<<dim3(8, Bn), 256>>>(nullptr, 8);

        // ---- cross attention ----
        gemm_qkv_kernel<<<dim3(4, 64, 3), 256, GEMM_SMEM>>>(xt, enct,
            wcaq + l * WSTRIDE, wcak + l * WSTRIDE, wcav + l * WSTRIDE,
            ca_bq + l * BSTRIDE, ca_bk + l * BSTRIDE, ca_bv + l * BSTRIDE);
        attn_kernel<<<Bn * Hn, 256, ATTN_SMEM>>>();
        ln_norm_kernel<<<dim3(8, Bn), 256>>>(nullptr, 8);

        // ---- feed forward ----
        gemm_ff1_kernel<<<dim3(FFn / 128, (Bn * Tn) / 128), 256, GEMM_SMEM>>>(
            xt, wff1 + (size_t)l * Cn * FFn, ff_b1 + (size_t)l * FFn);
        gemm_ff2_kernel<<<dim3(Cn / 128, (Bn * Tn) / 128), 256, GEMM_SMEM>>>(
            wff2 + (size_t)l * FFn * Cn, ff_b2 + (size_t)l * Cn);
        ln_norm_kernel<<<dim3(8, Bn), 256>>>((l == Ln - 1) ? out : nullptr, 4);
    }
}

// round 17
// speedup vs baseline: 1.5176x; 1.0248x over previous
#include <cuda_runtime.h>
#include <cuda_fp16.h>

#define Bn 64
#define Tn 128
#define Sn 128
#define Cn 512
#define Hn 8
#define DHn 64
#define FFn 2048
#define Ln 6

// ---------------- scratch (device globals; no allocation allowed) ----------------
__device__ __half g_qkvh[(size_t)Bn*Tn*1536]; // fused qkv output [B*T][q|k|v : 1536] fp16
__device__ float g_y[Bn*Tn*Cn];               // pre-norm y = x + residual (fp32)
__device__ __half g_h[(size_t)Bn*Tn*FFn];     // FF hidden (fp16)
__device__ __half g_xt[Bn*Tn*Cn];             // fp16 mirror of normalized x
__device__ __half g_enct[Bn*Sn*Cn];           // fp16 mirror of encoder output
__device__ float g_ps[Bn*8], g_ps2[Bn*8];     // LN partial stats (slots)
__device__ float g_mu[Bn], g_inv[Bn];         // committed LN stats of previous stage
// fp16 weights: qkv packed [L][1536][512] (rows: q 0-511 | k 512-1023 | v 1024-1535), k-contig
__device__ __half g_wsa[(size_t)Ln*1536*Cn];
__device__ __half g_wca[(size_t)Ln*1536*Cn];
__device__ __half g_wff1[(size_t)Ln*Cn*FFn];  // [L][FF][C]
__device__ __half g_wff2[(size_t)Ln*FFn*Cn];  // [L][C][FF]
__device__ float g_bsa[Ln*1536], g_bca[Ln*1536];  // concatenated q|k|v biases

// ---------------- helpers ----------------
__device__ __forceinline__ void mma16(float c[4], const unsigned a[4], const unsigned b[2]) {
    asm volatile("mma.sync.aligned.m16n8k16.row.col.f32.f16.f16.f32 "
        "{%0,%1,%2,%3}, {%4,%5,%6,%7}, {%8,%9}, {%0,%1,%2,%3};"
        : "+f"(c[0]), "+f"(c[1]), "+f"(c[2]), "+f"(c[3])
        : "r"(a[0]), "r"(a[1]), "r"(a[2]), "r"(a[3]), "r"(b[0]), "r"(b[1]));
}
__device__ __forceinline__ void cpasync16(void* s, const void* g) {
    unsigned sa = (unsigned)__cvta_generic_to_shared(s);
    asm volatile("cp.async.cg.shared.global [%0], [%1], 16;" :: "r"(sa), "l"(g));
}

// ---------------- one-time conversion kernels ----------------
__global__ void cvt_h_kernel(const float* __restrict__ src, __half* __restrict__ dst, int n) {
    int i = blockIdx.x * 256 + threadIdx.x;
    if (i < n) dst[i] = __float2half_rn(src[i]);
}
// tiled transpose-convert: [R][C] fp32 -> [C][R] fp16, batched with split z-stride
__global__ void tcvt_kernel(const float* __restrict__ src, __half* __restrict__ dst,
                            int R, int C, size_t sstride,
                            size_t dstrideL, size_t dstrideH, int zdiv)
{
    __shared__ float tile[32][33];
    int z = blockIdx.z;
    const float* s = src + (size_t)z * sstride;
    __half* d = dst + (size_t)(z / zdiv) * dstrideL + (size_t)(z % zdiv) * dstrideH;
    int r0 = blockIdx.y * 32, c0 = blockIdx.x * 32;
    int tx = threadIdx.x;
    #pragma unroll
    for (int i = threadIdx.y; i < 32; i += 8)
        tile[i][tx] = s[(size_t)(r0 + i) * C + c0 + tx];
    __syncthreads();
    #pragma unroll
    for (int i = threadIdx.y; i < 32; i += 8)
        d[(size_t)(c0 + i) * R + r0 + tx] = __float2half_rn(tile[tx][i]);
}
// concatenate per-head q/k/v biases into [L][1536]
__global__ void cat_bias_kernel(const float* __restrict__ bq, const float* __restrict__ bk,
                                const float* __restrict__ bv, float* __restrict__ dst)
{
    int i = blockIdx.x * 256 + threadIdx.x;   // < Ln*1536
    if (i >= Ln * 1536) return;
    int l = i / 1536, r = i - l * 1536;
    int seg = r >> 9, idx = r & 511;
    const float* src = (seg == 0) ? bq : (seg == 1) ? bk : bv;
    dst[i] = src[l * 512 + idx];
}
__global__ void init_stats_kernel() {
    int i = threadIdx.x;
    if (i < Bn) { g_mu[i] = 0.f; g_inv[i] = 1.f; }
}

// ------ fp16 GEMM: block 128x128, warp 64x32, m16n8k16, 3-stage cp.async --------------
// A [M][K] fp16 row-major; W [N][K] fp16 (k contiguous). smem stride 40 halves: all
// fragment LDS conflict-free (bank pattern 4g+t covers 32 banks).
#define RSH 40
#define TBUF (128*RSH)
#define NSTG 3
#define GEMM_SMEM (NSTG * 2 * TBUF * (int)sizeof(__half))   // 61440 B

// EPI: 1 = relu -> fp16 out, 2 = residual-from-y + LN stats (fp32), 3 = bias -> fp16 out
template<int EPI>
__device__ __forceinline__ void gemm_core(
    const __half* __restrict__ A, const __half* __restrict__ W,
    const float* __restrict__ bias, void* __restrict__ outp,
    int OSTR, int K, int rowTile, int colTile, __half* smem)
{
    __half* As = smem;
    __half* Bs = smem + NSTG * TBUF;

    int tid = threadIdx.x, wid = tid >> 5, lane = tid & 31;
    int wm = wid >> 2, wn = wid & 3;
    int g = lane >> 2, t = lane & 3;

    float acc[4][4][4];
    #pragma unroll
    for (int i = 0; i < 4; i++)
        #pragma unroll
        for (int j = 0; j < 4; j++)
            #pragma unroll
            for (int q = 0; q < 4; q++) acc[i][j][q] = 0.f;

    const __half* Ab = A + (size_t)rowTile * K;
    const __half* Wb = W + (size_t)colTile * K;
    int KT = K >> 5;

    #pragma unroll
    for (int st = 0; st < 2; st++) {
        int k0 = st << 5;
        __half* Ad = As + st * TBUF;
        __half* Bd = Bs + st * TBUF;
        #pragma unroll
        for (int j = 0; j < 2; j++) {
            int q = tid + j * 256; int r = q >> 2, ko = (q & 3) * 8;
            cpasync16(&Ad[r * RSH + ko], &Ab[(size_t)r * K + k0 + ko]);
        }
        #pragma unroll
        for (int j = 0; j < 2; j++) {
            int q = tid + j * 256; int r = q >> 2, ko = (q & 3) * 8;
            cpasync16(&Bd[r * RSH + ko], &Wb[(size_t)r * K + k0 + ko]);
        }
        asm volatile("cp.async.commit_group;");
    }

    int buf = 0;
    for (int kt = 0; kt < KT; kt++) {
        asm volatile("cp.async.wait_group 1;");
        __syncthreads();

        const unsigned* Au = (const unsigned*)(As + buf * TBUF);
        const unsigned* Bu = (const unsigned*)(Bs + buf * TBUF);
        #pragma unroll
        for (int ks = 0; ks < 2; ks++) {
            int c = ks * 8 + t;
            unsigned a[4][4], bfr[4][2];
            #pragma unroll
            for (int i = 0; i < 4; i++) {
                int r = wm * 64 + i * 16 + g;
                a[i][0] = Au[r * 20 + c];
                a[i][1] = Au[(r + 8) * 20 + c];
                a[i][2] = Au[r * 20 + c + 4];
                a[i][3] = Au[(r + 8) * 20 + c + 4];
            }
            #pragma unroll
            for (int j = 0; j < 4; j++) {
                int n = wn * 32 + j * 8 + g;
                bfr[j][0] = Bu[n * 20 + c];
                bfr[j][1] = Bu[n * 20 + c + 4];
            }
            #pragma unroll
            for (int i = 0; i < 4; i++)
                #pragma unroll
                for (int j = 0; j < 4; j++)
                    mma16(acc[i][j], a[i], bfr[j]);
        }

        if (kt + 2 < KT) {
            int k0 = (kt + 2) << 5;
            int nb = kt + 2; nb -= (nb / NSTG) * NSTG;
            __half* Ad = As + nb * TBUF;
            __half* Bd = Bs + nb * TBUF;
            #pragma unroll
            for (int j = 0; j < 2; j++) {
                int q = tid + j * 256; int r = q >> 2, ko = (q & 3) * 8;
                cpasync16(&Ad[r * RSH + ko], &Ab[(size_t)r * K + k0 + ko]);
            }
            #pragma unroll
            for (int j = 0; j < 2; j++) {
                int q = tid + j * 256; int r = q >> 2, ko = (q & 3) * 8;
                cpasync16(&Bd[r * RSH + ko], &Wb[(size_t)r * K + k0 + ko]);
            }
        }
        asm volatile("cp.async.commit_group;");

        buf++; if (buf == NSTG) buf = 0;
    }

    float s = 0.f, s2 = 0.f;
    float mu = 0.f, inv = 1.f;
    if (EPI == 2) { mu = g_mu[rowTile >> 7]; inv = g_inv[rowTile >> 7]; }
    #pragma unroll
    for (int i = 0; i < 4; i++) {
        int r0 = rowTile + wm * 64 + i * 16 + g;
        #pragma unroll
        for (int j = 0; j < 4; j++) {
            int c = colTile + wn * 32 + j * 8 + 2 * t;
            float b0 = bias[c], b1 = bias[c + 1];
            float v0 = acc[i][j][0] + b0, v1 = acc[i][j][1] + b1;
            float v2 = acc[i][j][2] + b0, v3 = acc[i][j][3] + b1;
            if (EPI == 1 || EPI == 3) {
                __half2* oh = (__half2*)outp;
                if (EPI == 1) {
                    v0 = fmaxf(v0, 0.f); v1 = fmaxf(v1, 0.f);
                    v2 = fmaxf(v2, 0.f); v3 = fmaxf(v3, 0.f);
                }
                oh[((size_t)r0 * OSTR + c) >> 1]       = __floats2half2_rn(v0, v1);
                oh[((size_t)(r0 + 8) * OSTR + c) >> 1] = __floats2half2_rn(v2, v3);
            } else {
                float* of = (float*)outp;
                const float* resid = (const float*)outp;  // g_y in-place
                float2 x0 = *(const float2*)&resid[(size_t)r0 * OSTR + c];
                float2 x1 = *(const float2*)&resid[(size_t)(r0 + 8) * OSTR + c];
                v0 += (x0.x - mu) * inv; v1 += (x0.y - mu) * inv;
                v2 += (x1.x - mu) * inv; v3 += (x1.y - mu) * inv;
                s  += v0 + v1 + v2 + v3;
                s2 += v0*v0 + v1*v1 + v2*v2 + v3*v3;
                *(float2*)&of[(size_t)r0 * OSTR + c]       = make_float2(v0, v1);
                *(float2*)&of[(size_t)(r0 + 8) * OSTR + c] = make_float2(v2, v3);
            }
        }
    }

    if (EPI == 2) {
        __shared__ float rs[8], rs2[8];
        #pragma unroll
        for (int o = 16; o > 0; o >>= 1) {
            s  += __shfl_xor_sync(0xffffffffu, s, o);
            s2 += __shfl_xor_sync(0xffffffffu, s2, o);
        }
        if (lane == 0) { rs[wid] = s; rs2[wid] = s2; }
        __syncthreads();
        if (tid == 0) {
            float ts = 0.f, ts2 = 0.f;
            #pragma unroll
            for (int i = 0; i < 8; i++) { ts += rs[i]; ts2 += rs2[i]; }
            int slot = (rowTile >> 7) * 8 + (colTile >> 7);
            g_ps[slot] = ts; g_ps2[slot] = ts2;
        }
    }
}

// fused qkv projection: out fp16 into g_qkvh (row stride 1536) at column offset colBase
__global__ __launch_bounds__(256, 2) void gemm_qkv_kernel(
    const __half* __restrict__ A, const __half* __restrict__ W,
    const float* __restrict__ bias, __half* __restrict__ outp)
{
    extern __shared__ __half hsmem[];
    gemm_core<3>(A, W, bias, outp, 1536, 512,
                 blockIdx.y * 128, blockIdx.x * 128, hsmem);
}
__global__ __launch_bounds__(256, 2) void gemm_ff1_kernel(
    const __half* __restrict__ A, const __half* __restrict__ W,
    const float* __restrict__ bias)
{
    extern __shared__ __half hsmem[];
    gemm_core<1>(A, W, bias, g_h, FFn, Cn,
                 blockIdx.y * 128, blockIdx.x * 128, hsmem);
}
__global__ __launch_bounds__(256, 2) void gemm_ff2_kernel(
    const __half* __restrict__ W, const float* __restrict__ bias)
{
    extern __shared__ __half hsmem[];
    gemm_core<2>(g_h, W, bias, g_y, Cn, FFn,
                 blockIdx.y * 128, blockIdx.x * 128, hsmem);
}

// ------- fp16 fused attention per (b,h) + residual-from-y add + LN stats --------------
// smem (halves): Qh[128][72] | Kh[128][72] | Vt[64][136] | Ps fp32[128][132] | Ph[128][136]
#define QHS 72
#define VTS 136
#define PSS 132
#define PHS 136
#define OFF_KH  (128*QHS)             // 9216
#define OFF_VT  (2*128*QHS)           // 18432
#define OFF_PS  (OFF_VT + 64*VTS)     // 27136 (halves; byte 54272, 4B aligned)
#define OFF_PH  (OFF_PS + 128*PSS*2)  // 60928
#define ATTN_SMEM ((OFF_PH + 128*PHS) * (int)sizeof(__half))  // 156672 B

__global__ __launch_bounds__(256) void attn_kernel()
{
    extern __shared__ __half hsm[];
    __half* Qh = hsm;
    __half* Kh = hsm + OFF_KH;
    __half* Vt = hsm + OFF_VT;
    float*  Ps = (float*)(hsm + OFF_PS);
    __half* Ph = hsm + OFF_PH;

    int bh = blockIdx.x;
    int h = bh & (Hn - 1);
    int b = bh >> 3;
    int tid = threadIdx.x, wid = tid >> 5, lane = tid & 31;
    int g = lane >> 2, t = lane & 3;

    const __half* qb = g_qkvh + (size_t)b * Tn * 1536 + h * DHn;
    const __half* kb = qb + 512;
    const __half* vb = qb + 1024;

    // stage: Q,K straight (16B copies); V transposed to [d][s]
    for (int e = tid; e < 1024; e += 256) {
        int r = e >> 3, ch = (e & 7) * 8;
        *(float4*)&Qh[r * QHS + ch] = *(const float4*)&qb[(size_t)r * 1536 + ch];
        *(float4*)&Kh[r * QHS + ch] = *(const float4*)&kb[(size_t)r * 1536 + ch];
        int sR = e & 127, dch = (e >> 7) * 8;
        __half tmp[8];
        *(float4*)tmp = *(const float4*)&vb[(size_t)sR * 1536 + dch];
        #pragma unroll
        for (int i = 0; i < 8; i++) Vt[(dch + i) * VTS + sR] = tmp[i];
    }
    __syncthreads();

    // ---- scores = Q @ K^T (scaled 1/8 at write): 128x128, k=64 -> 4 k16 steps ----
    {
        int wm = wid >> 2, wn = wid & 3;       // warp tile 64x32
        float acc[4][4][4];
        #pragma unroll
        for (int i = 0; i < 4; i++)
            #pragma unroll
            for (int j = 0; j < 4; j++)
                #pragma unroll
                for (int q = 0; q < 4; q++) acc[i][j][q] = 0.f;

        const unsigned* Qu = (const unsigned*)Qh;   // stride 36 unsigned
        const unsigned* Ku = (const unsigned*)Kh;
        #pragma unroll
        for (int ks = 0; ks < 4; ks++) {
            int c = ks * 8 + t;
            unsigned a[4][4], bfr[4][2];
            #pragma unroll
            for (int i = 0; i < 4; i++) {
                int r = wm * 64 + i * 16 + g;
                a[i][0] = Qu[r * 36 + c];
                a[i][1] = Qu[(r + 8) * 36 + c];
                a[i][2] = Qu[r * 36 + c + 4];
                a[i][3] = Qu[(r + 8) * 36 + c + 4];
            }
            #pragma unroll
            for (int j = 0; j < 4; j++) {
                int n = wn * 32 + j * 8 + g;
                bfr[j][0] = Ku[n * 36 + c];
                bfr[j][1] = Ku[n * 36 + c + 4];
            }
            #pragma unroll
            for (int i = 0; i < 4; i++)
                #pragma unroll
                for (int j = 0; j < 4; j++)
                    mma16(acc[i][j], a[i], bfr[j]);
        }
        #pragma unroll
        for (int i = 0; i < 4; i++) {
            int r0 = wm * 64 + i * 16 + g;
            #pragma unroll
            for (int j = 0; j < 4; j++) {
                int c = wn * 32 + j * 8 + 2 * t;
                *(float2*)&Ps[r0 * PSS + c]       = make_float2(acc[i][j][0] * 0.125f, acc[i][j][1] * 0.125f);
                *(float2*)&Ps[(r0 + 8) * PSS + c] = make_float2(acc[i][j][2] * 0.125f, acc[i][j][3] * 0.125f);
            }
        }
    }
    __syncthreads();

    // ---- softmax (fp32), write fp16 P ----
    {
        int row = tid >> 1;
        const float* p = Ps + row * PSS + (tid & 1) * 64;
        __half2* ph = (__half2*)(Ph + row * PHS + (tid & 1) * 64);
        float mx = -1e30f;
        #pragma unroll 8
        for (int j = 0; j < 64; j++) mx = fmaxf(mx, p[j]);
        mx = fmaxf(mx, __shfl_xor_sync(0xffffffffu, mx, 1));
        float buf[64];
        float s = 0.f;
        #pragma unroll 8
        for (int j = 0; j < 64; j++) { float e = __expf(p[j] - mx); buf[j] = e; s += e; }
        s += __shfl_xor_sync(0xffffffffu, s, 1);
        float inv = 1.f / s;
        #pragma unroll 8
        for (int j = 0; j < 32; j++)
            ph[j] = __floats2half2_rn(buf[2*j] * inv, buf[2*j+1] * inv);
    }
    __syncthreads();

    // ---- O = P @ V^T-layout : 128x64, k=128 -> 8 k16 steps. warps 4(M)x2(N) ----
    {
        int wm = wid >> 1, wn = wid & 1;       // warp tile 32x32
        float acc[2][4][4];
        #pragma unroll
        for (int i = 0; i < 2; i++)
            #pragma unroll
            for (int j = 0; j < 4; j++)
                #pragma unroll
                for (int q = 0; q < 4; q++) acc[i][j][q] = 0.f;

        const unsigned* Pu = (const unsigned*)Ph;   // stride 68 unsigned
        const unsigned* Vu = (const unsigned*)Vt;   // stride 68 unsigned
        #pragma unroll
        for (int ks = 0; ks < 8; ks++) {
            int c = ks * 8 + t;
            unsigned a[2][4], bfr[4][2];
            #pragma unroll
            for (int i = 0; i < 2; i++) {
                int r = wm * 32 + i * 16 + g;
                a[i][0] = Pu[r * 68 + c];
                a[i][1] = Pu[(r + 8) * 68 + c];
                a[i][2] = Pu[r * 68 + c + 4];
                a[i][3] = Pu[(r + 8) * 68 + c + 4];
            }
            #pragma unroll
            for (int j = 0; j < 4; j++) {
                int n = wn * 32 + j * 8 + g;    // d index
                bfr[j][0] = Vu[n * 68 + c];
                bfr[j][1] = Vu[n * 68 + c + 4];
            }
            #pragma unroll
            for (int i = 0; i < 2; i++)
                #pragma unroll
                for (int j = 0; j < 4; j++)
                    mma16(acc[i][j], a[i], bfr[j]);
        }

        float mu = g_mu[b], inv = g_inv[b];
        float* og = g_y + (size_t)b * Tn * Cn + (size_t)h * DHn;
        float s = 0.f, s2 = 0.f;
        #pragma unroll
        for (int i = 0; i < 2; i++) {
            int r0 = wm * 32 + i * 16 + g;
            #pragma unroll
            for (int j = 0; j < 4; j++) {
                int c = wn * 32 + j * 8 + 2 * t;
                float2 x0 = *(const float2*)&og[(size_t)r0 * Cn + c];
                float2 x1 = *(const float2*)&og[(size_t)(r0 + 8) * Cn + c];
                float v0 = acc[i][j][0] + (x0.x - mu) * inv;
                float v1 = acc[i][j][1] + (x0.y - mu) * inv;
                float v2 = acc[i][j][2] + (x1.x - mu) * inv;
                float v3 = acc[i][j][3] + (x1.y - mu) * inv;
                s  += v0 + v1 + v2 + v3;
                s2 += v0*v0 + v1*v1 + v2*v2 + v3*v3;
                *(float2*)&og[(size_t)r0 * Cn + c]       = make_float2(v0, v1);
                *(float2*)&og[(size_t)(r0 + 8) * Cn + c] = make_float2(v2, v3);
            }
        }

        __shared__ float rs[8], rs2[8];
        #pragma unroll
        for (int o = 16; o > 0; o >>= 1) {
            s  += __shfl_xor_sync(0xffffffffu, s, o);
            s2 += __shfl_xor_sync(0xffffffffu, s2, o);
        }
        if (lane == 0) { rs[wid] = s; rs2[wid] = s2; }
        __syncthreads();
        if (tid == 0) {
            float ts = 0.f, ts2 = 0.f;
            #pragma unroll
            for (int i = 0; i < 8; i++) { ts += rs[i]; ts2 += rs2[i]; }
            g_ps[b*8 + h] = ts; g_ps2[b*8 + h] = ts2;
        }
    }
}

// --------- LN: slots -> (mu,inv); y -> xt (fp16), optional fp32 out -------------------
__global__ __launch_bounds__(256) void ln_norm_kernel(float* __restrict__ xout, int nslots)
{
    int b = blockIdx.y, chunk = blockIdx.x;
    float s = 0.f, s2 = 0.f;
    for (int i = 0; i < nslots; i++) { s += g_ps[b*8 + i]; s2 += g_ps2[b*8 + i]; }
    const float invN = 1.f / (Tn * Cn);
    float mu  = s * invN;
    float var = s2 * invN - mu * mu;
    float inv = rsqrtf(var + 1e-5f);
    if (chunk == 0 && threadIdx.x == 0) { g_mu[b] = mu; g_inv[b] = inv; }

    size_t base4 = ((size_t)b * Tn * Cn + (size_t)chunk * (Tn * Cn / 8)) / 4;
    const float4* y4 = (const float4*)g_y + base4;
    __half2* xt2 = (__half2*)g_xt + base4 * 2;
    const int n4 = Tn * Cn / 8 / 4;
    int tid = threadIdx.x;
    if (xout) {
        float4* x4 = (float4*)xout + base4;
        for (int i = tid; i < n4; i += 256) {
            float4 a = y4[i];
            a.x = (a.x - mu) * inv; a.y = (a.y - mu) * inv;
            a.z = (a.z - mu) * inv; a.w = (a.w - mu) * inv;
            x4[i] = a;
            xt2[2*i]   = __floats2half2_rn(a.x, a.y);
            xt2[2*i+1] = __floats2half2_rn(a.z, a.w);
        }
    } else {
        for (int i = tid; i < n4; i += 256) {
            float4 a = y4[i];
            xt2[2*i]   = __floats2half2_rn((a.x - mu) * inv, (a.y - mu) * inv);
            xt2[2*i+1] = __floats2half2_rn((a.z - mu) * inv, (a.w - mu) * inv);
        }
    }
}

// ---------------- driver ----------------
extern "C" void kernel_launch(void* const* d_in, const int* in_sizes, int n_in,
                              void* d_out, int out_size)
{
    const float* x     = (const float*)d_in[0];
    const float* enc   = (const float*)d_in[1];
    const float* sa_wq = (const float*)d_in[2];  const float* sa_bq = (const float*)d_in[3];
    const float* sa_wk = (const float*)d_in[4];  const float* sa_bk = (const float*)d_in[5];
    const float* sa_wv = (const float*)d_in[6];  const float* sa_bv = (const float*)d_in[7];
    const float* ca_wq = (const float*)d_in[8];  const float* ca_bq = (const float*)d_in[9];
    const float* ca_wk = (const float*)d_in[10]; const float* ca_bk = (const float*)d_in[11];
    const float* ca_wv = (const float*)d_in[12]; const float* ca_bv = (const float*)d_in[13];
    const float* ff_w1 = (const float*)d_in[14]; const float* ff_b1 = (const float*)d_in[15];
    const float* ff_w2 = (const float*)d_in[16]; const float* ff_b2 = (const float*)d_in[17];
    float* out = (float*)d_out;

    cudaFuncSetAttribute(attn_kernel, cudaFuncAttributeMaxDynamicSharedMemorySize, ATTN_SMEM);
    cudaFuncSetAttribute(gemm_qkv_kernel, cudaFuncAttributeMaxDynamicSharedMemorySize, GEMM_SMEM);
    cudaFuncSetAttribute(gemm_ff1_kernel, cudaFuncAttributeMaxDynamicSharedMemorySize, GEMM_SMEM);
    cudaFuncSetAttribute(gemm_ff2_kernel, cudaFuncAttributeMaxDynamicSharedMemorySize, GEMM_SMEM);

    __half *wsa, *wca, *wff1, *wff2, *xt, *enct, *qkvh;
    float *yb, *bsa, *bca;
    cudaGetSymbolAddress((void**)&wsa,  g_wsa);
    cudaGetSymbolAddress((void**)&wca,  g_wca);
    cudaGetSymbolAddress((void**)&wff1, g_wff1);
    cudaGetSymbolAddress((void**)&wff2, g_wff2);
    cudaGetSymbolAddress((void**)&xt,   g_xt);
    cudaGetSymbolAddress((void**)&enct, g_enct);
    cudaGetSymbolAddress((void**)&yb,   g_y);
    cudaGetSymbolAddress((void**)&bsa,  g_bsa);
    cudaGetSymbolAddress((void**)&bca,  g_bca);
    cudaGetSymbolAddress((void**)&qkvh, g_qkvh);

    const int nAct = Bn * Tn * Cn;
    cudaMemcpyAsync(yb, x, sizeof(float) * nAct, cudaMemcpyDeviceToDevice);
    init_stats_kernel<<<1, 64>>>();
    cvt_h_kernel<<<(nAct + 255) / 256, 256>>>(x, xt, nAct);
    cvt_h_kernel<<<(nAct + 255) / 256, 256>>>(enc, enct, nAct);

    // qkv weights -> [L][1536][512] (seg offset via dst base), per (l,h) transpose
    dim3 tb(32, 8);
    const size_t DL = (size_t)1536 * Cn;   // per-layer dst stride
    const size_t DH_ = (size_t)DHn * Cn;   // per-head dst stride
    const size_t SEG = (size_t)512 * Cn;   // per-segment (q/k/v) offset
    tcvt_kernel<<<dim3(DHn/32, Cn/32, Ln*Hn), tb>>>(sa_wq, wsa,         Cn, DHn, (size_t)Cn*DHn, DL, DH_, Hn);
    tcvt_kernel<<<dim3(DHn/32, Cn/32, Ln*Hn), tb>>>(sa_wk, wsa + SEG,   Cn, DHn, (size_t)Cn*DHn, DL, DH_, Hn);
    tcvt_kernel<<<dim3(DHn/32, Cn/32, Ln*Hn), tb>>>(sa_wv, wsa + 2*SEG, Cn, DHn, (size_t)Cn*DHn, DL, DH_, Hn);
    tcvt_kernel<<<dim3(DHn/32, Cn/32, Ln*Hn), tb>>>(ca_wq, wca,         Cn, DHn, (size_t)Cn*DHn, DL, DH_, Hn);
    tcvt_kernel<<<dim3(DHn/32, Cn/32, Ln*Hn), tb>>>(ca_wk, wca + SEG,   Cn, DHn, (size_t)Cn*DHn, DL, DH_, Hn);
    tcvt_kernel<<<dim3(DHn/32, Cn/32, Ln*Hn), tb>>>(ca_wv, wca + 2*SEG, Cn, DHn, (size_t)Cn*DHn, DL, DH_, Hn);
    tcvt_kernel<<<dim3(FFn/32, Cn/32, Ln), tb>>>(ff_w1, wff1, Cn, FFn, (size_t)Cn*FFn, (size_t)Cn*FFn, 0, 1);
    tcvt_kernel<<<dim3(Cn/32, FFn/32, Ln), tb>>>(ff_w2, wff2, FFn, Cn, (size_t)FFn*Cn, (size_t)FFn*Cn, 0, 1);
    cat_bias_kernel<<<(Ln*1536 + 255)/256, 256>>>(sa_bq, sa_bk, sa_bv, bsa);
    cat_bias_kernel<<<(Ln*1536 + 255)/256, 256>>>(ca_bq, ca_bk, ca_bv, bca);

    for (int l = 0; l < Ln; l++) {
        // ---- self attention: fused QKV (N=1536) ----
        gemm_qkv_kernel<<<dim3(12, 64), 256, GEMM_SMEM>>>(
            xt, wsa + (size_t)l * DL, bsa + l * 1536, qkvh);
        attn_kernel<<<Bn * Hn, 256, ATTN_SMEM>>>();
        ln_norm_kernel<<<dim3(8, Bn), 256>>>(nullptr, 8);

        // ---- cross attention: q from xt (N=512), kv from enct (N=1024) ----
        gemm_qkv_kernel<<<dim3(4, 64), 256, GEMM_SMEM>>>(
            xt, wca + (size_t)l * DL, bca + l * 1536, qkvh);
        gemm_qkv_kernel<<<dim3(8, 64), 256, GEMM_SMEM>>>(
            enct, wca + (size_t)l * DL + SEG, bca + l * 1536 + 512, qkvh + 512);
        attn_kernel<<<Bn * Hn, 256, ATTN_SMEM>>>();
        ln_norm_kernel<<<dim3(8, Bn), 256>>>(nullptr, 8);

        // ---- feed forward ----
        gemm_ff1_kernel<<<dim3(FFn / 128, (Bn * Tn) / 128), 256, GEMM_SMEM>>>(
            xt, wff1 + (size_t)l * Cn * FFn, ff_b1 + (size_t)l * FFn);
        gemm_ff2_kernel<<<dim3(Cn / 128, (Bn * Tn) / 128), 256, GEMM_SMEM>>>(
            wff2 + (size_t)l * FFn * Cn, ff_b2 + (size_t)l * Cn);
        ln_norm_kernel<<<dim3(8, Bn), 256>>>((l == Ln - 1) ? out : nullptr, 4);
    }
}